// round 1
// baseline (speedup 1.0000x reference)
#include <cuda_runtime.h>
#include <cuda_bf16.h>
#include <math.h>

#define S_LEN 4096
#define HID   2048
#define NH    16
#define NKV   4
#define HD    128
#define NBLK  32          // S_LEN / 128
#define NEGV  -1000000000.0f
#define SCALE 0.08838834764831845f   // HD^-0.5

// ---------------- scratch (static device globals; no runtime alloc) ----------
__device__ float g_Q[S_LEN * NH * HD];          // 32 MB
__device__ float g_K[S_LEN * NKV * HD];         // 8 MB
__device__ float g_V[S_LEN * NKV * HD];         // 8 MB
__device__ float g_S[(size_t)NH * NBLK * 128 * 1024];  // 256 MB (scores -> probs in place)
__device__ float g_O[S_LEN * NH * HD];          // 32 MB

// --------------- key-block schedule --------------------------------------
// j in [0,4): local blocks n-3+j ; j in [4,8): global blocks [0, clip(n-24), clip(n-16), clip(n-8)]
__device__ __forceinline__ int key_block(int n, int j, bool* valid) {
    if (j < 4) {
        int kb = n - 3 + j;
        *valid = (kb >= 0);
        return kb < 0 ? 0 : kb;
    }
    int jj = j - 4;
    if (jj == 0) { *valid = true; return 0; }
    int off = (4 - jj) * 8;            // jj=1:24, jj=2:16, jj=3:8
    int kb = n - off; if (kb < 0) kb = 0;
    int kprev;
    if (jj == 1) kprev = 0;
    else { int po = (5 - jj) * 8; kprev = n - po; if (kprev < 0) kprev = 0; }
    *valid = (kb != kprev);
    return kb;
}

// --------------- generic fp32 NN GEMM: C[M,N] = A[M,K] * B[K,N] -----------
// 128x128 tile, BK=16, 256 threads, 8x8 per-thread microtile
__global__ void gemm_nn_kernel(const float* __restrict__ A,
                               const float* __restrict__ B,
                               float* __restrict__ C,
                               int M, int N, int K) {
    __shared__ float As[16][132];
    __shared__ float Bs[16][132];
    int bx = blockIdx.x, by = blockIdx.y;
    int tid = threadIdx.x;
    int tx = tid & 15, ty = tid >> 4;
    float acc[8][8];
#pragma unroll
    for (int i = 0; i < 8; i++)
#pragma unroll
        for (int j = 0; j < 8; j++) acc[i][j] = 0.f;

    const float* Ab = A + (size_t)(by * 128) * K;
    const float* Bb = B + (size_t)bx * 128;

    for (int k0 = 0; k0 < K; k0 += 16) {
#pragma unroll
        for (int i = 0; i < 2; i++) {
            int idx = tid + i * 256;
            int ar = idx >> 2, ac = (idx & 3) * 4;
            float4 a = *(const float4*)(Ab + (size_t)ar * K + k0 + ac);
            As[ac + 0][ar] = a.x; As[ac + 1][ar] = a.y;
            As[ac + 2][ar] = a.z; As[ac + 3][ar] = a.w;
        }
#pragma unroll
        for (int i = 0; i < 2; i++) {
            int idx = tid + i * 256;
            int br = idx >> 5, bc = (idx & 31) * 4;
            *(float4*)&Bs[br][bc] = *(const float4*)(Bb + (size_t)(k0 + br) * N + bc);
        }
        __syncthreads();
#pragma unroll
        for (int kk = 0; kk < 16; kk++) {
            float a[8], b[8];
            *(float4*)(a)     = *(float4*)&As[kk][ty * 8];
            *(float4*)(a + 4) = *(float4*)&As[kk][ty * 8 + 4];
            *(float4*)(b)     = *(float4*)&Bs[kk][tx * 8];
            *(float4*)(b + 4) = *(float4*)&Bs[kk][tx * 8 + 4];
#pragma unroll
            for (int i = 0; i < 8; i++)
#pragma unroll
                for (int j = 0; j < 8; j++) acc[i][j] += a[i] * b[j];
        }
        __syncthreads();
    }
#pragma unroll
    for (int i = 0; i < 8; i++) {
        float* Cp = C + (size_t)(by * 128 + ty * 8 + i) * N + bx * 128 + tx * 8;
        float4 c0 = make_float4(acc[i][0], acc[i][1], acc[i][2], acc[i][3]);
        float4 c1 = make_float4(acc[i][4], acc[i][5], acc[i][6], acc[i][7]);
        *(float4*)(Cp)     = c0;
        *(float4*)(Cp + 4) = c1;
    }
}

// --------------- RoPE (+ optional score scaling) --------------------------
__global__ void rope_kernel(float* __restrict__ X,
                            const float* __restrict__ cosb,
                            const float* __restrict__ sinb,
                            int nheads, float scale) {
    int idx = blockIdx.x * blockDim.x + threadIdx.x;
    int total = S_LEN * nheads * 64;
    if (idx >= total) return;
    int d = idx & 63;
    int hh = (idx >> 6) % nheads;
    int s = idx / (64 * nheads);
    float c1 = cosb[s * HD + d],      s1 = sinb[s * HD + d];
    float c2 = cosb[s * HD + d + 64], s2 = sinb[s * HD + d + 64];
    float* p = X + (size_t)s * (nheads * HD) + hh * HD + d;
    float x1 = p[0], x2 = p[64];
    p[0]  = (x1 * c1 - x2 * s1) * scale;
    p[64] = (x2 * c2 + x1 * s2) * scale;
}

// --------------- scores: S[h,n,t, j*128+s] = Qb @ Kblk^T + bias -----------
__global__ void scores_kernel(const float* __restrict__ Q,
                              const float* __restrict__ Kmat,
                              const float* __restrict__ mask,
                              float* __restrict__ S) {
    int j = blockIdx.x, n = blockIdx.y, h = blockIdx.z;
    bool valid; int kb = key_block(n, j, &valid);
    size_t srowbase = (size_t)((h * NBLK + n) * 128);

    if (!valid) {
        for (int idx = threadIdx.x; idx < 128 * 128; idx += 256) {
            int t = idx >> 7, s = idx & 127;
            S[(srowbase + t) * 1024 + j * 128 + s] = NEGV;
        }
        return;
    }
    int kvh = h >> 2;
    __shared__ float As[16][132];
    __shared__ float Bs[16][132];
    int tid = threadIdx.x;
    int tx = tid & 15, ty = tid >> 4;
    float acc[8][8];
#pragma unroll
    for (int i = 0; i < 8; i++)
#pragma unroll
        for (int c = 0; c < 8; c++) acc[i][c] = 0.f;

    const float* Qb = Q + (size_t)(n * 128) * (NH * HD) + h * HD;
    const float* Kb = Kmat + (size_t)(kb * 128) * (NKV * HD) + kvh * HD;

    for (int k0 = 0; k0 < HD; k0 += 16) {
#pragma unroll
        for (int i = 0; i < 2; i++) {
            int idx = tid + i * 256;
            int ar = idx >> 2, ac = (idx & 3) * 4;
            float4 a = *(const float4*)(Qb + (size_t)ar * (NH * HD) + k0 + ac);
            As[ac + 0][ar] = a.x; As[ac + 1][ar] = a.y;
            As[ac + 2][ar] = a.z; As[ac + 3][ar] = a.w;
            float4 b = *(const float4*)(Kb + (size_t)ar * (NKV * HD) + k0 + ac);
            Bs[ac + 0][ar] = b.x; Bs[ac + 1][ar] = b.y;
            Bs[ac + 2][ar] = b.z; Bs[ac + 3][ar] = b.w;
        }
        __syncthreads();
#pragma unroll
        for (int kk = 0; kk < 16; kk++) {
            float a[8], b[8];
            *(float4*)(a)     = *(float4*)&As[kk][ty * 8];
            *(float4*)(a + 4) = *(float4*)&As[kk][ty * 8 + 4];
            *(float4*)(b)     = *(float4*)&Bs[kk][tx * 8];
            *(float4*)(b + 4) = *(float4*)&Bs[kk][tx * 8 + 4];
#pragma unroll
            for (int i = 0; i < 8; i++)
#pragma unroll
                for (int c = 0; c < 8; c++) acc[i][c] += a[i] * b[c];
        }
        __syncthreads();
    }
    // epilogue: mask bias + causal on last local block (j==3)
#pragma unroll
    for (int i = 0; i < 8; i++) {
        int t = ty * 8 + i;
#pragma unroll
        for (int c = 0; c < 8; c++) {
            int s = tx * 8 + c;
            float v = acc[i][c] + (1.0f - mask[kb * 128 + s]) * NEGV;
            if (j == 3 && s > t) v += NEGV;
            S[(srowbase + t) * 1024 + j * 128 + s] = v;
        }
    }
}

// --------------- softmax over 1024 keys, warp per row ---------------------
__global__ void softmax_kernel(float* __restrict__ S) {
    int r = blockIdx.x * 8 + (threadIdx.x >> 5);
    int lane = threadIdx.x & 31;
    float* row = S + (size_t)r * 1024;
    float v[32];
    float m = -3.4e38f;
#pragma unroll
    for (int i = 0; i < 32; i++) {
        v[i] = row[lane + i * 32];
        m = fmaxf(m, v[i]);
    }
#pragma unroll
    for (int o = 16; o > 0; o >>= 1) m = fmaxf(m, __shfl_xor_sync(0xffffffffu, m, o));
    float sum = 0.f;
#pragma unroll
    for (int i = 0; i < 32; i++) {
        v[i] = __expf(v[i] - m);
        sum += v[i];
    }
#pragma unroll
    for (int o = 16; o > 0; o >>= 1) sum += __shfl_xor_sync(0xffffffffu, sum, o);
    float inv = 1.0f / sum;
#pragma unroll
    for (int i = 0; i < 32; i++) row[lane + i * 32] = v[i] * inv;
}

// --------------- PV: O[h,n] = P(128x1024) @ Vgather(1024x128) -------------
__global__ void pv_kernel(const float* __restrict__ P,
                          const float* __restrict__ V,
                          float* __restrict__ O) {
    int n = blockIdx.x, h = blockIdx.y;
    int kvh = h >> 2;
    __shared__ float As[16][132];
    __shared__ float Bs[16][132];
    int tid = threadIdx.x;
    int tx = tid & 15, ty = tid >> 4;
    float acc[8][8];
#pragma unroll
    for (int i = 0; i < 8; i++)
#pragma unroll
        for (int c = 0; c < 8; c++) acc[i][c] = 0.f;

    const float* Pb = P + (size_t)((h * NBLK + n) * 128) * 1024;

    for (int k0 = 0; k0 < 1024; k0 += 16) {
        int j = k0 >> 7;
        bool valid; int kb = key_block(n, j, &valid);  // invalid -> P rows are 0, clamp kb
#pragma unroll
        for (int i = 0; i < 2; i++) {
            int idx = tid + i * 256;
            int ar = idx >> 2, ac = (idx & 3) * 4;
            float4 a = *(const float4*)(Pb + (size_t)ar * 1024 + k0 + ac);
            As[ac + 0][ar] = a.x; As[ac + 1][ar] = a.y;
            As[ac + 2][ar] = a.z; As[ac + 3][ar] = a.w;
            int br = idx >> 5, bc = (idx & 31) * 4;
            *(float4*)&Bs[br][bc] =
                *(const float4*)(V + (size_t)(kb * 128 + (k0 & 127) + br) * (NKV * HD) + kvh * HD + bc);
        }
        __syncthreads();
#pragma unroll
        for (int kk = 0; kk < 16; kk++) {
            float a[8], b[8];
            *(float4*)(a)     = *(float4*)&As[kk][ty * 8];
            *(float4*)(a + 4) = *(float4*)&As[kk][ty * 8 + 4];
            *(float4*)(b)     = *(float4*)&Bs[kk][tx * 8];
            *(float4*)(b + 4) = *(float4*)&Bs[kk][tx * 8 + 4];
#pragma unroll
            for (int i = 0; i < 8; i++)
#pragma unroll
                for (int c = 0; c < 8; c++) acc[i][c] += a[i] * b[c];
        }
        __syncthreads();
    }
#pragma unroll
    for (int i = 0; i < 8; i++) {
        float* Op = O + (size_t)(n * 128 + ty * 8 + i) * (NH * HD) + h * HD + tx * 8;
        float4 c0 = make_float4(acc[i][0], acc[i][1], acc[i][2], acc[i][3]);
        float4 c1 = make_float4(acc[i][4], acc[i][5], acc[i][6], acc[i][7]);
        *(float4*)(Op)     = c0;
        *(float4*)(Op + 4) = c1;
    }
}

// ----------------------------- launch ------------------------------------
extern "C" void kernel_launch(void* const* d_in, const int* in_sizes, int n_in,
                              void* d_out, int out_size) {
    const float* H    = (const float*)d_in[0];   // (1,4096,2048)
    const float* mask = (const float*)d_in[1];   // (1,4096)
    const float* cosb = (const float*)d_in[2];   // (1,4096,128)
    const float* sinb = (const float*)d_in[3];   // (1,4096,128)
    const float* Wq   = (const float*)d_in[4];   // (2048,2048)
    const float* Wk   = (const float*)d_in[5];   // (2048,512)
    const float* Wv   = (const float*)d_in[6];   // (2048,512)
    const float* Wo   = (const float*)d_in[7];   // (2048,2048)
    float* out = (float*)d_out;

    float *Qs, *Ks, *Vs, *Ss, *Os;
    cudaGetSymbolAddress((void**)&Qs, g_Q);
    cudaGetSymbolAddress((void**)&Ks, g_K);
    cudaGetSymbolAddress((void**)&Vs, g_V);
    cudaGetSymbolAddress((void**)&Ss, g_S);
    cudaGetSymbolAddress((void**)&Os, g_O);

    // 1) projections
    gemm_nn_kernel<<<dim3(16, 32), 256>>>(H, Wq, Qs, S_LEN, NH * HD, HID);
    gemm_nn_kernel<<<dim3(4, 32), 256>>>(H, Wk, Ks, S_LEN, NKV * HD, HID);
    gemm_nn_kernel<<<dim3(4, 32), 256>>>(H, Wv, Vs, S_LEN, NKV * HD, HID);

    // 2) RoPE (+ fold score scaling into Q)
    {
        int totQ = S_LEN * NH * 64;
        rope_kernel<<<(totQ + 255) / 256, 256>>>(Qs, cosb, sinb, NH, SCALE);
        int totK = S_LEN * NKV * 64;
        rope_kernel<<<(totK + 255) / 256, 256>>>(Ks, cosb, sinb, NKV, 1.0f);
    }

    // 3) scores (QK^T with mask/causal bias)
    scores_kernel<<<dim3(8, NBLK, NH), 256>>>(Qs, Ks, mask, Ss);

    // 4) softmax
    softmax_kernel<<<(NH * NBLK * 128) / 8, 256>>>(Ss);

    // 5) PV
    pv_kernel<<<dim3(NBLK, NH), 256>>>(Ss, Vs, Os);

    // 6) output projection
    gemm_nn_kernel<<<dim3(16, 32), 256>>>(Os, Wo, out, S_LEN, HID, NH * HD);
}

// round 3
// speedup vs baseline: 2.7786x; 2.7786x over previous
#include <cuda_runtime.h>
#include <cuda_bf16.h>
#include <cstdint>

#define S_LEN 4096
#define HID   2048
#define NH    16
#define NKV   4
#define HD    128
#define NBLK  32
#define NEGV  -1000000000.0f
#define SCALE 0.08838834764831845f   // HD^-0.5

// ---------------- scratch ----------------
__device__ float g_Q[S_LEN * NH * HD];                 // 32 MB
__device__ float g_K[S_LEN * NKV * HD];                // 8 MB
__device__ float g_V[S_LEN * NKV * HD];                // 8 MB
__device__ float g_S[(size_t)NH * NBLK * 128 * 1024];  // 256 MB
__device__ float g_O[S_LEN * NH * HD];                 // 32 MB
__device__ float g_WqT[HID * NH * HD];
__device__ float g_WkT[HID * NKV * HD];
__device__ float g_WvT[HID * NKV * HD];
__device__ float g_WoT[(size_t)NH * HD * HID];
__device__ float g_VT[(size_t)NKV * HD * S_LEN];

// ---------------- helpers ----------------
__device__ __forceinline__ uint32_t smem_u32(const void* p) {
    uint32_t a;
    asm("{ .reg .u64 t; cvta.to.shared.u64 t, %1; cvt.u32.u64 %0, t; }" : "=r"(a) : "l"(p));
    return a;
}
__device__ __forceinline__ uint32_t tf32_rna(float x) {
    uint32_t u;
    asm("cvt.rna.tf32.f32 %0, %1;" : "=r"(u) : "f"(x));
    return u;
}
__device__ __forceinline__ void cp16(uint32_t dst, const float* src) {
    asm volatile("cp.async.cg.shared.global [%0], [%1], 16;" :: "r"(dst), "l"(src));
}
#define CP_COMMIT() asm volatile("cp.async.commit_group;" ::: "memory")

__device__ __forceinline__ void mma_tf32(float c[4], uint32_t a0, uint32_t a1,
                                         uint32_t a2, uint32_t a3,
                                         uint32_t b0, uint32_t b1) {
    asm volatile(
        "mma.sync.aligned.m16n8k8.row.col.f32.tf32.tf32.f32 "
        "{%0,%1,%2,%3}, {%4,%5,%6,%7}, {%8,%9}, {%0,%1,%2,%3};"
        : "+f"(c[0]), "+f"(c[1]), "+f"(c[2]), "+f"(c[3])
        : "r"(a0), "r"(a1), "r"(a2), "r"(a3), "r"(b0), "r"(b1));
}

// ---------------- key-block schedule ----------------
__device__ __forceinline__ int key_block(int n, int j, bool* valid) {
    if (j < 4) {
        int kb = n - 3 + j;
        *valid = (kb >= 0);
        return kb < 0 ? 0 : kb;
    }
    int jj = j - 4;
    if (jj == 0) { *valid = true; return 0; }
    int off = (4 - jj) * 8;
    int kb = n - off; if (kb < 0) kb = 0;
    int kprev;
    if (jj == 1) kprev = 0;
    else { int po = (5 - jj) * 8; kprev = n - po; if (kprev < 0) kprev = 0; }
    *valid = (kb != kprev);
    return kb;
}

// ---------------- operand functors ----------------
struct Lin {
    const float* base; int ld;
    __device__ __forceinline__ const float* operator()(int r, int kc) const {
        return base + (size_t)r * ld + kc * 32;
    }
};
struct PVB {
    const float* vt; int n;
    __device__ __forceinline__ const float* operator()(int r, int kc) const {
        int j = kc >> 2; bool v; int kb = key_block(n, j, &v);
        return vt + (size_t)r * S_LEN + kb * 128 + (kc & 3) * 32;
    }
};

// ---------------- shared tile addressing (XOR swizzled) -------------------
// stage layout: A tile 128x32 floats (16KB), B tile 128x32 floats (16KB)
// phys word(r, k) = r*32 + 4*((k>>2) ^ (r&7)) + (k&3)
#define STAGE_BYTES 32768
#define SMEM_BYTES  65536
__device__ __forceinline__ int sadr(int r, int k) {
    return r * 32 + (((k >> 2) ^ (r & 7)) << 2) + (k & 3);
}

template <class AF, class BF>
__device__ __forceinline__ void fill_stage(uint32_t st, const AF& af, const BF& bf,
                                           int kc, int tid) {
#pragma unroll
    for (int i = 0; i < 4; i++) {
        int idx = tid + i * 256;
        int r = idx >> 3, c4 = idx & 7;
        uint32_t off = (uint32_t)(r * 32 + ((c4 ^ (r & 7)) << 2)) * 4;
        cp16(st + off, af(r, kc) + c4 * 4);
        cp16(st + 16384 + off, bf(r, kc) + c4 * 4);
    }
}

__device__ __forceinline__ void compute_stage(const float* sA, const float* sB,
                                              float acc[4][4][4], int lane,
                                              int wmoff, int wnoff) {
#pragma unroll
    for (int ks = 0; ks < 4; ks++) {
        int k0 = ks * 8 + (lane & 3);
        int k1 = k0 + 4;
        uint32_t a[4][4], b[4][2];
#pragma unroll
        for (int mt = 0; mt < 4; mt++) {
            int r0 = wmoff + mt * 16 + (lane >> 2);
            a[mt][0] = tf32_rna(sA[sadr(r0, k0)]);
            a[mt][1] = tf32_rna(sA[sadr(r0 + 8, k0)]);
            a[mt][2] = tf32_rna(sA[sadr(r0, k1)]);
            a[mt][3] = tf32_rna(sA[sadr(r0 + 8, k1)]);
        }
#pragma unroll
        for (int nt = 0; nt < 4; nt++) {
            int n0 = wnoff + nt * 8 + (lane >> 2);
            b[nt][0] = tf32_rna(sB[sadr(n0, k0)]);
            b[nt][1] = tf32_rna(sB[sadr(n0, k1)]);
        }
#pragma unroll
        for (int mt = 0; mt < 4; mt++)
#pragma unroll
            for (int nt = 0; nt < 4; nt++)
                mma_tf32(acc[mt][nt], a[mt][0], a[mt][1], a[mt][2], a[mt][3],
                         b[nt][0], b[nt][1]);
    }
}

template <class AF, class BF>
__device__ __forceinline__ void gemm_core(const AF& af, const BF& bf, int nch,
                                          float acc[4][4][4], char* smem) {
    int tid = threadIdx.x;
    int lane = tid & 31, wid = tid >> 5;
    int wmoff = (wid & 1) * 64, wnoff = (wid >> 1) * 32;
#pragma unroll
    for (int mt = 0; mt < 4; mt++)
#pragma unroll
        for (int nt = 0; nt < 4; nt++)
#pragma unroll
            for (int c = 0; c < 4; c++) acc[mt][nt][c] = 0.f;

    uint32_t sb = smem_u32(smem);
    fill_stage(sb, af, bf, 0, tid);
    CP_COMMIT();
    for (int kc = 0; kc < nch; kc++) {
        int s = kc & 1;
        if (kc + 1 < nch) {
            fill_stage(sb + (s ^ 1) * STAGE_BYTES, af, bf, kc + 1, tid);
            CP_COMMIT();
            asm volatile("cp.async.wait_group 1;" ::: "memory");
        } else {
            asm volatile("cp.async.wait_group 0;" ::: "memory");
        }
        __syncthreads();
        const float* sA = (const float*)(smem + s * STAGE_BYTES);
        compute_stage(sA, sA + 4096, acc, lane, wmoff, wnoff);
        __syncthreads();
    }
}

// ---------------- generic GEMM: C[M,N] = A[M,K] @ BT[N,K]^T ---------------
__global__ void __launch_bounds__(256) gemm_tc_kernel(const float* __restrict__ A,
                                                      const float* __restrict__ BT,
                                                      float* __restrict__ C,
                                                      int K, int N) {
    extern __shared__ char smem[];
    float acc[4][4][4];
    Lin af{A + (size_t)(blockIdx.y * 128) * K, K};
    Lin bf{BT + (size_t)(blockIdx.x * 128) * K, K};
    gemm_core(af, bf, K / 32, acc, smem);

    int lane = threadIdx.x & 31, wid = threadIdx.x >> 5;
    int row0 = blockIdx.y * 128 + (wid & 1) * 64 + (lane >> 2);
    int col0 = blockIdx.x * 128 + (wid >> 1) * 32 + 2 * (lane & 3);
#pragma unroll
    for (int mt = 0; mt < 4; mt++)
#pragma unroll
        for (int nt = 0; nt < 4; nt++) {
            float* p = C + (size_t)(row0 + mt * 16) * N + col0 + nt * 8;
            *(float2*)p = make_float2(acc[mt][nt][0], acc[mt][nt][1]);
            *(float2*)(p + 8 * (size_t)N) = make_float2(acc[mt][nt][2], acc[mt][nt][3]);
        }
}

// ---------------- scores ----------------
__global__ void __launch_bounds__(256) scores_tc_kernel(const float* __restrict__ Q,
                                                        const float* __restrict__ Kmat,
                                                        const float* __restrict__ mask,
                                                        float* __restrict__ S) {
    int j = blockIdx.x, n = blockIdx.y, h = blockIdx.z;
    bool valid; int kb = key_block(n, j, &valid);
    size_t srowbase = (size_t)((h * NBLK + n) * 128);
    if (!valid) {
        for (int idx = threadIdx.x; idx < 128 * 128; idx += 256) {
            int t = idx >> 7, s = idx & 127;
            S[(srowbase + t) * 1024 + j * 128 + s] = NEGV;
        }
        return;
    }
    extern __shared__ char smem[];
    float acc[4][4][4];
    int kvh = h >> 2;
    Lin af{Q + (size_t)(n * 128) * (NH * HD) + h * HD, NH * HD};
    Lin bf{Kmat + (size_t)(kb * 128) * (NKV * HD) + kvh * HD, NKV * HD};
    gemm_core(af, bf, HD / 32, acc, smem);

    int lane = threadIdx.x & 31, wid = threadIdx.x >> 5;
    int t0 = (wid & 1) * 64 + (lane >> 2);
    int s0 = (wid >> 1) * 32 + 2 * (lane & 3);
#pragma unroll
    for (int mt = 0; mt < 4; mt++)
#pragma unroll
        for (int nt = 0; nt < 4; nt++) {
            int t = t0 + mt * 16;
            int s = s0 + nt * 8;
            float m0 = (1.0f - mask[kb * 128 + s]) * NEGV;
            float m1 = (1.0f - mask[kb * 128 + s + 1]) * NEGV;
            float v0 = acc[mt][nt][0] + m0, v1 = acc[mt][nt][1] + m1;
            float v2 = acc[mt][nt][2] + m0, v3 = acc[mt][nt][3] + m1;
            if (j == 3) {
                if (s > t) v0 += NEGV;
                if (s + 1 > t) v1 += NEGV;
                if (s > t + 8) v2 += NEGV;
                if (s + 1 > t + 8) v3 += NEGV;
            }
            float* p = S + (srowbase + t) * 1024 + j * 128 + s;
            *(float2*)p = make_float2(v0, v1);
            *(float2*)(p + 8 * 1024) = make_float2(v2, v3);
        }
}

// ---------------- PV ----------------
__global__ void __launch_bounds__(256) pv_tc_kernel(const float* __restrict__ P,
                                                    const float* __restrict__ VT,
                                                    float* __restrict__ O) {
    int n = blockIdx.x, h = blockIdx.y;
    extern __shared__ char smem[];
    float acc[4][4][4];
    int kvh = h >> 2;
    Lin af{P + (size_t)((h * NBLK + n) * 128) * 1024, 1024};
    PVB bf{VT + (size_t)kvh * HD * S_LEN, n};
    gemm_core(af, bf, 1024 / 32, acc, smem);

    int lane = threadIdx.x & 31, wid = threadIdx.x >> 5;
    int row0 = n * 128 + (wid & 1) * 64 + (lane >> 2);
    int col0 = h * HD + (wid >> 1) * 32 + 2 * (lane & 3);
#pragma unroll
    for (int mt = 0; mt < 4; mt++)
#pragma unroll
        for (int nt = 0; nt < 4; nt++) {
            float* p = O + (size_t)(row0 + mt * 16) * (NH * HD) + col0 + nt * 8;
            *(float2*)p = make_float2(acc[mt][nt][0], acc[mt][nt][1]);
            *(float2*)(p + 8 * (size_t)(NH * HD)) = make_float2(acc[mt][nt][2], acc[mt][nt][3]);
        }
}

// ---------------- transpose: dst[C][R] = src[R][C] ------------------------
__global__ void transpose_kernel(const float* __restrict__ src, float* __restrict__ dst,
                                 int R, int C) {
    __shared__ float t[32][33];
    int bx = blockIdx.x * 32, by = blockIdx.y * 32;
    int x = bx + threadIdx.x;
#pragma unroll
    for (int i = 0; i < 32; i += 8) {
        int y = by + threadIdx.y + i;
        t[threadIdx.y + i][threadIdx.x] = src[(size_t)y * C + x];
    }
    __syncthreads();
    int x2 = by + threadIdx.x;
#pragma unroll
    for (int i = 0; i < 32; i += 8) {
        int y2 = bx + threadIdx.y + i;
        dst[(size_t)y2 * R + x2] = t[threadIdx.x][threadIdx.y + i];
    }
}

// ---------------- RoPE ----------------------------------------------------
__global__ void rope_kernel(float* __restrict__ X,
                            const float* __restrict__ cosb,
                            const float* __restrict__ sinb,
                            int nheads, float scale) {
    int idx = blockIdx.x * blockDim.x + threadIdx.x;
    int total = S_LEN * nheads * 64;
    if (idx >= total) return;
    int d = idx & 63;
    int hh = (idx >> 6) % nheads;
    int s = idx / (64 * nheads);
    float c1 = cosb[s * HD + d],      s1 = sinb[s * HD + d];
    float c2 = cosb[s * HD + d + 64], s2 = sinb[s * HD + d + 64];
    float* p = X + (size_t)s * (nheads * HD) + hh * HD + d;
    float x1 = p[0], x2 = p[64];
    p[0]  = (x1 * c1 - x2 * s1) * scale;
    p[64] = (x2 * c2 + x1 * s2) * scale;
}

// ---------------- softmax over 1024 keys, warp per row --------------------
__global__ void softmax_kernel(float* __restrict__ S) {
    int r = blockIdx.x * 8 + (threadIdx.x >> 5);
    int lane = threadIdx.x & 31;
    float* row = S + (size_t)r * 1024;
    float v[32];
    float m = -3.4e38f;
#pragma unroll
    for (int i = 0; i < 32; i++) {
        v[i] = row[lane + i * 32];
        m = fmaxf(m, v[i]);
    }
#pragma unroll
    for (int o = 16; o > 0; o >>= 1) m = fmaxf(m, __shfl_xor_sync(0xffffffffu, m, o));
    float sum = 0.f;
#pragma unroll
    for (int i = 0; i < 32; i++) {
        v[i] = __expf(v[i] - m);
        sum += v[i];
    }
#pragma unroll
    for (int o = 16; o > 0; o >>= 1) sum += __shfl_xor_sync(0xffffffffu, sum, o);
    float inv = 1.0f / sum;
#pragma unroll
    for (int i = 0; i < 32; i++) row[lane + i * 32] = v[i] * inv;
}

// ---------------- launch --------------------------------------------------
extern "C" void kernel_launch(void* const* d_in, const int* in_sizes, int n_in,
                              void* d_out, int out_size) {
    const float* H    = (const float*)d_in[0];
    const float* mask = (const float*)d_in[1];
    const float* cosb = (const float*)d_in[2];
    const float* sinb = (const float*)d_in[3];
    const float* Wq   = (const float*)d_in[4];
    const float* Wk   = (const float*)d_in[5];
    const float* Wv   = (const float*)d_in[6];
    const float* Wo   = (const float*)d_in[7];
    float* out = (float*)d_out;

    float *Qs, *Ks, *Vs, *Ss, *Os, *WqT, *WkT, *WvT, *WoT, *VTs;
    cudaGetSymbolAddress((void**)&Qs, g_Q);
    cudaGetSymbolAddress((void**)&Ks, g_K);
    cudaGetSymbolAddress((void**)&Vs, g_V);
    cudaGetSymbolAddress((void**)&Ss, g_S);
    cudaGetSymbolAddress((void**)&Os, g_O);
    cudaGetSymbolAddress((void**)&WqT, g_WqT);
    cudaGetSymbolAddress((void**)&WkT, g_WkT);
    cudaGetSymbolAddress((void**)&WvT, g_WvT);
    cudaGetSymbolAddress((void**)&WoT, g_WoT);
    cudaGetSymbolAddress((void**)&VTs, g_VT);

    cudaFuncSetAttribute(gemm_tc_kernel,   cudaFuncAttributeMaxDynamicSharedMemorySize, SMEM_BYTES);
    cudaFuncSetAttribute(scores_tc_kernel, cudaFuncAttributeMaxDynamicSharedMemorySize, SMEM_BYTES);
    cudaFuncSetAttribute(pv_tc_kernel,     cudaFuncAttributeMaxDynamicSharedMemorySize, SMEM_BYTES);

    dim3 tb(32, 8);
    transpose_kernel<<<dim3(64, 64), tb>>>(Wq, WqT, HID, NH * HD);
    transpose_kernel<<<dim3(16, 64), tb>>>(Wk, WkT, HID, NKV * HD);
    transpose_kernel<<<dim3(16, 64), tb>>>(Wv, WvT, HID, NKV * HD);
    transpose_kernel<<<dim3(64, 64), tb>>>(Wo, WoT, NH * HD, HID);

    gemm_tc_kernel<<<dim3(16, 32), 256, SMEM_BYTES>>>(H, WqT, Qs, HID, NH * HD);
    gemm_tc_kernel<<<dim3(4, 32), 256, SMEM_BYTES>>>(H, WkT, Ks, HID, NKV * HD);
    gemm_tc_kernel<<<dim3(4, 32), 256, SMEM_BYTES>>>(H, WvT, Vs, HID, NKV * HD);

    rope_kernel<<<(S_LEN * NH * 64 + 255) / 256, 256>>>(Qs, cosb, sinb, NH, SCALE);
    rope_kernel<<<(S_LEN * NKV * 64 + 255) / 256, 256>>>(Ks, cosb, sinb, NKV, 1.0f);

    transpose_kernel<<<dim3(16, 128), tb>>>(Vs, VTs, S_LEN, NKV * HD);

    scores_tc_kernel<<<dim3(8, NBLK, NH), 256, SMEM_BYTES>>>(Qs, Ks, mask, Ss);
    softmax_kernel<<<(NH * NBLK * 128) / 8, 256>>>(Ss);
    pv_tc_kernel<<<dim3(NBLK, NH), 256, SMEM_BYTES>>>(Ss, VTs, Os);

    gemm_tc_kernel<<<dim3(16, 32), 256, SMEM_BYTES>>>(Os, WoT, out, NH * HD, HID);
}

// round 4
// speedup vs baseline: 4.4415x; 1.5985x over previous
#include <cuda_runtime.h>
#include <cstdint>

#define S_LEN 4096
#define HID   2048
#define NH    16
#define NKV   4
#define HD    128
#define NBLK  32
#define NEGV  -1000000000.0f
#define SCALE 0.08838834764831845f   // HD^-0.5

// ---------------- scratch ----------------
__device__ float g_Hr[S_LEN * HID];                    // pre-rounded H (32 MB)
__device__ float g_Q[S_LEN * NH * HD];                 // 32 MB
__device__ float g_K[S_LEN * NKV * HD];                // 8 MB
__device__ float g_V[S_LEN * NKV * HD];                // 8 MB
__device__ float g_O[S_LEN * NH * HD];                 // 32 MB
__device__ float g_WqT[HID * NH * HD];
__device__ float g_WkT[HID * NKV * HD];
__device__ float g_WvT[HID * NKV * HD];
__device__ float g_WoT[(size_t)NH * HD * HID];
__device__ float g_VT[(size_t)NKV * HD * S_LEN];

// ---------------- helpers ----------------
__device__ __forceinline__ uint32_t smem_u32(const void* p) {
    uint32_t a;
    asm("{ .reg .u64 t; cvta.to.shared.u64 t, %1; cvt.u32.u64 %0, t; }" : "=r"(a) : "l"(p));
    return a;
}
__device__ __forceinline__ uint32_t tf32_rna_u(float x) {
    uint32_t u;
    asm("cvt.rna.tf32.f32 %0, %1;" : "=r"(u) : "f"(x));
    return u;
}
__device__ __forceinline__ float tf32_rna_f(float x) { return __uint_as_float(tf32_rna_u(x)); }

__device__ __forceinline__ void cp16(uint32_t dst, const float* src) {
    asm volatile("cp.async.cg.shared.global [%0], [%1], 16;" :: "r"(dst), "l"(src));
}
#define CP_COMMIT() asm volatile("cp.async.commit_group;" ::: "memory")
#define CP_WAIT1()  asm volatile("cp.async.wait_group 1;" ::: "memory")
#define CP_WAIT0()  asm volatile("cp.async.wait_group 0;" ::: "memory")

__device__ __forceinline__ void mma_tf32(float c[4], uint32_t a0, uint32_t a1,
                                         uint32_t a2, uint32_t a3,
                                         uint32_t b0, uint32_t b1) {
    asm volatile(
        "mma.sync.aligned.m16n8k8.row.col.f32.tf32.tf32.f32 "
        "{%0,%1,%2,%3}, {%4,%5,%6,%7}, {%8,%9}, {%0,%1,%2,%3};"
        : "+f"(c[0]), "+f"(c[1]), "+f"(c[2]), "+f"(c[3])
        : "r"(a0), "r"(a1), "r"(a2), "r"(a3), "r"(b0), "r"(b1));
}
__device__ __forceinline__ void ldm_x4(uint32_t r[4], uint32_t addr) {
    asm volatile("ldmatrix.sync.aligned.m8n8.x4.shared.b16 {%0,%1,%2,%3}, [%4];"
                 : "=r"(r[0]), "=r"(r[1]), "=r"(r[2]), "=r"(r[3]) : "r"(addr));
}

// ---------------- key-block schedule ----------------
__device__ __forceinline__ int key_block(int n, int j, bool* valid) {
    if (j < 4) {
        int kb = n - 3 + j;
        *valid = (kb >= 0);
        return kb < 0 ? 0 : kb;
    }
    int jj = j - 4;
    if (jj == 0) { *valid = true; return 0; }
    int off = (4 - jj) * 8;
    int kb = n - off; if (kb < 0) kb = 0;
    int kprev;
    if (jj == 1) kprev = 0;
    else { int po = (5 - jj) * 8; kprev = n - po; if (kprev < 0) kprev = 0; }
    *valid = (kb != kprev);
    return kb;
}

// ---------------- smem tile: 128 rows x 32 floats, XOR swizzled -----------
// word(r,k) = r*32 + ((k>>2)^(r&7))*4 + (k&3)
__device__ __forceinline__ void fill_tile(uint32_t st, const float* src, int stride, int tid) {
#pragma unroll
    for (int i = 0; i < 4; i++) {
        int idx = tid + i * 256;
        int r = idx >> 3, c4 = idx & 7;
        cp16(st + 4u * (uint32_t)(r * 32 + ((c4 ^ (r & 7)) << 2)),
             src + (size_t)r * stride + c4 * 4);
    }
}

// ---------------- ldmatrix-based 128x128x32 compute -----------------------
__device__ __forceinline__ void compute_tile(uint32_t aB, uint32_t bB,
                                             float acc[4][4][4],
                                             int lane, int wm, int wn) {
    int quad = lane >> 3;
    int l7 = lane & 7;
    int aRow = wm + ((quad & 1) << 3) + l7;
    int aKh = quad >> 1;
    int bRow = wn + ((quad >> 1) << 3) + l7;
    int bKh = quad & 1;
#pragma unroll
    for (int ks = 0; ks < 4; ks++) {
        uint32_t a[4][4], b[2][4];
#pragma unroll
        for (int mt = 0; mt < 4; mt++) {
            uint32_t w = (uint32_t)((aRow + mt * 16) * 32 + (((ks * 2 + aKh) ^ l7) << 2));
            ldm_x4(a[mt], aB + 4u * w);
        }
#pragma unroll
        for (int np = 0; np < 2; np++) {
            uint32_t w = (uint32_t)((bRow + np * 16) * 32 + (((ks * 2 + bKh) ^ l7) << 2));
            ldm_x4(b[np], bB + 4u * w);
        }
#pragma unroll
        for (int mt = 0; mt < 4; mt++)
#pragma unroll
            for (int np = 0; np < 2; np++) {
                mma_tf32(acc[mt][np * 2],     a[mt][0], a[mt][1], a[mt][2], a[mt][3],
                         b[np][0], b[np][1]);
                mma_tf32(acc[mt][np * 2 + 1], a[mt][0], a[mt][1], a[mt][2], a[mt][3],
                         b[np][2], b[np][3]);
            }
    }
}

// ---------------- generic GEMM: C[M,N] = A[M,K] @ BT[N,K]^T ---------------
#define GEMM_SMEM 65536
__global__ void __launch_bounds__(256) gemm_tc_kernel(const float* __restrict__ A,
                                                      const float* __restrict__ BT,
                                                      float* __restrict__ C,
                                                      int K, int N) {
    extern __shared__ char smem[];
    uint32_t sb = smem_u32(smem);
    int tid = threadIdx.x, lane = tid & 31, wid = tid >> 5;
    int wm = (wid & 1) * 64, wn = (wid >> 1) * 32;
    float acc[4][4][4];
#pragma unroll
    for (int mt = 0; mt < 4; mt++)
#pragma unroll
        for (int nt = 0; nt < 4; nt++)
#pragma unroll
            for (int c = 0; c < 4; c++) acc[mt][nt][c] = 0.f;

    const float* Ab = A + (size_t)(blockIdx.y * 128) * K;
    const float* Bb = BT + (size_t)(blockIdx.x * 128) * K;
    int nch = K / 32;
    fill_tile(sb, Ab, K, tid);
    fill_tile(sb + 16384, Bb, K, tid);
    CP_COMMIT();
    for (int kc = 0; kc < nch; kc++) {
        int s = kc & 1;
        if (kc + 1 < nch) {
            uint32_t st = sb + (s ^ 1) * 32768;
            fill_tile(st, Ab + (kc + 1) * 32, K, tid);
            fill_tile(st + 16384, Bb + (kc + 1) * 32, K, tid);
            CP_COMMIT();
            CP_WAIT1();
        } else CP_WAIT0();
        __syncthreads();
        compute_tile(sb + s * 32768, sb + s * 32768 + 16384, acc, lane, wm, wn);
        __syncthreads();
    }
    int row0 = blockIdx.y * 128 + wm + (lane >> 2);
    int col0 = blockIdx.x * 128 + wn + 2 * (lane & 3);
#pragma unroll
    for (int mt = 0; mt < 4; mt++)
#pragma unroll
        for (int nt = 0; nt < 4; nt++) {
            float* p = C + (size_t)(row0 + mt * 16) * N + col0 + nt * 8;
            *(float2*)p = make_float2(acc[mt][nt][0], acc[mt][nt][1]);
            *(float2*)(p + 8 * (size_t)N) = make_float2(acc[mt][nt][2], acc[mt][nt][3]);
        }
}

// ---------------- fused flash attention -----------------------------------
// smem: Q 4x16K | P 4x16K | stage 2x16K | redM 2K | redS 2K  = 167936 B
#define FL_SMEM 167936
__global__ void __launch_bounds__(256, 1) flash_kernel(const float* __restrict__ Q,
                                                       const float* __restrict__ Kmat,
                                                       const float* __restrict__ VT,
                                                       const float* __restrict__ mask,
                                                       float* __restrict__ O) {
    int n = blockIdx.x, h = blockIdx.y, kvh = h >> 2;
    extern __shared__ char smem[];
    uint32_t sb = smem_u32(smem);
    const uint32_t Qoff = 0, Poff = 65536, St0 = 131072;
    float* redM = (float*)(smem + 163840);
    float* redS = (float*)(smem + 165888);
    int tid = threadIdx.x, lane = tid & 31, wid = tid >> 5;
    int wm = (wid & 1) * 64, wn = (wid >> 1) * 32;
    int q2 = 2 * (lane & 3);

    // load Q tile (4 chunks)
    const float* Qb = Q + (size_t)(n * 128) * (NH * HD) + h * HD;
#pragma unroll
    for (int kc = 0; kc < 4; kc++) fill_tile(sb + Qoff + kc * 16384, Qb + kc * 32, NH * HD, tid);
    CP_COMMIT();
    CP_WAIT0();
    __syncthreads();

    float Oacc[4][4][4];
#pragma unroll
    for (int mt = 0; mt < 4; mt++)
#pragma unroll
        for (int nt = 0; nt < 4; nt++)
#pragma unroll
            for (int c = 0; c < 4; c++) Oacc[mt][nt][c] = 0.f;
    float m_r[4][2], l_r[4][2];
#pragma unroll
    for (int mt = 0; mt < 4; mt++) { m_r[mt][0] = m_r[mt][1] = -1e30f; l_r[mt][0] = l_r[mt][1] = 0.f; }

    for (int j = 0; j < 8; j++) {
        bool valid; int kb = key_block(n, j, &valid);
        if (!valid) continue;

        // ---- S = Q @ K_blk^T ----
        float Sacc[4][4][4];
#pragma unroll
        for (int mt = 0; mt < 4; mt++)
#pragma unroll
            for (int nt = 0; nt < 4; nt++)
#pragma unroll
                for (int c = 0; c < 4; c++) Sacc[mt][nt][c] = 0.f;
        const float* Kb = Kmat + (size_t)(kb * 128) * (NKV * HD) + kvh * HD;
        fill_tile(sb + St0, Kb, NKV * HD, tid);
        CP_COMMIT();
        for (int kc = 0; kc < 4; kc++) {
            if (kc < 3) {
                fill_tile(sb + St0 + ((kc + 1) & 1) * 16384, Kb + (kc + 1) * 32, NKV * HD, tid);
                CP_COMMIT();
                CP_WAIT1();
            } else CP_WAIT0();
            __syncthreads();
            compute_tile(sb + Qoff + kc * 16384, sb + St0 + (kc & 1) * 16384, Sacc, lane, wm, wn);
            __syncthreads();
        }

        // ---- bias: mask + causal (j==3) ----
        const float* mrow = mask + kb * 128;
#pragma unroll
        for (int nt = 0; nt < 4; nt++) {
            int s0 = wn + nt * 8 + q2;
            float b0 = (1.0f - mrow[s0]) * NEGV;
            float b1 = (1.0f - mrow[s0 + 1]) * NEGV;
#pragma unroll
            for (int mt = 0; mt < 4; mt++) {
                Sacc[mt][nt][0] += b0; Sacc[mt][nt][1] += b1;
                Sacc[mt][nt][2] += b0; Sacc[mt][nt][3] += b1;
            }
            if (j == 3) {
#pragma unroll
                for (int mt = 0; mt < 4; mt++) {
                    int t0 = wm + mt * 16 + (lane >> 2);
                    if (s0 > t0) Sacc[mt][nt][0] += NEGV;
                    if (s0 + 1 > t0) Sacc[mt][nt][1] += NEGV;
                    if (s0 > t0 + 8) Sacc[mt][nt][2] += NEGV;
                    if (s0 + 1 > t0 + 8) Sacc[mt][nt][3] += NEGV;
                }
            }
        }

        // ---- block row-max ----
        float bm[4][2];
#pragma unroll
        for (int mt = 0; mt < 4; mt++) {
            float v0 = -1e30f, v1 = -1e30f;
#pragma unroll
            for (int nt = 0; nt < 4; nt++) {
                v0 = fmaxf(v0, fmaxf(Sacc[mt][nt][0], Sacc[mt][nt][1]));
                v1 = fmaxf(v1, fmaxf(Sacc[mt][nt][2], Sacc[mt][nt][3]));
            }
            v0 = fmaxf(v0, __shfl_xor_sync(0xffffffffu, v0, 1));
            v0 = fmaxf(v0, __shfl_xor_sync(0xffffffffu, v0, 2));
            v1 = fmaxf(v1, __shfl_xor_sync(0xffffffffu, v1, 1));
            v1 = fmaxf(v1, __shfl_xor_sync(0xffffffffu, v1, 2));
            bm[mt][0] = v0; bm[mt][1] = v1;
        }
        if ((lane & 3) == 0) {
#pragma unroll
            for (int mt = 0; mt < 4; mt++)
#pragma unroll
                for (int hh = 0; hh < 2; hh++) {
                    int row = wm + mt * 16 + hh * 8 + (lane >> 2);
                    redM[row * 4 + (wid >> 1)] = bm[mt][hh];
                }
        }
        __syncthreads();

        float mnew[4][2], alpha[4][2];
#pragma unroll
        for (int mt = 0; mt < 4; mt++)
#pragma unroll
            for (int hh = 0; hh < 2; hh++) {
                int row = wm + mt * 16 + hh * 8 + (lane >> 2);
                float g = fmaxf(fmaxf(redM[row * 4], redM[row * 4 + 1]),
                                fmaxf(redM[row * 4 + 2], redM[row * 4 + 3]));
                g = fmaxf(g, m_r[mt][hh]);
                alpha[mt][hh] = __expf(m_r[mt][hh] - g);
                mnew[mt][hh] = g;
            }

        // ---- P = exp(S - m), rescale O, partial sums ----
        float ps[4][2];
#pragma unroll
        for (int mt = 0; mt < 4; mt++) { ps[mt][0] = 0.f; ps[mt][1] = 0.f; }
#pragma unroll
        for (int mt = 0; mt < 4; mt++)
#pragma unroll
            for (int nt = 0; nt < 4; nt++) {
                float p0 = __expf(Sacc[mt][nt][0] - mnew[mt][0]);
                float p1 = __expf(Sacc[mt][nt][1] - mnew[mt][0]);
                float p2 = __expf(Sacc[mt][nt][2] - mnew[mt][1]);
                float p3 = __expf(Sacc[mt][nt][3] - mnew[mt][1]);
                Sacc[mt][nt][0] = p0; Sacc[mt][nt][1] = p1;
                Sacc[mt][nt][2] = p2; Sacc[mt][nt][3] = p3;
                ps[mt][0] += p0 + p1; ps[mt][1] += p2 + p3;
                Oacc[mt][nt][0] *= alpha[mt][0]; Oacc[mt][nt][1] *= alpha[mt][0];
                Oacc[mt][nt][2] *= alpha[mt][1]; Oacc[mt][nt][3] *= alpha[mt][1];
            }
#pragma unroll
        for (int mt = 0; mt < 4; mt++)
#pragma unroll
            for (int hh = 0; hh < 2; hh++) {
                float v = ps[mt][hh];
                v += __shfl_xor_sync(0xffffffffu, v, 1);
                v += __shfl_xor_sync(0xffffffffu, v, 2);
                ps[mt][hh] = v;
            }
        if ((lane & 3) == 0) {
#pragma unroll
            for (int mt = 0; mt < 4; mt++)
#pragma unroll
                for (int hh = 0; hh < 2; hh++) {
                    int row = wm + mt * 16 + hh * 8 + (lane >> 2);
                    redS[row * 4 + (wid >> 1)] = ps[mt][hh];
                }
        }

        // ---- store P to smem (own chunk = wid>>1), rounded ----
        uint32_t pchunk = sb + Poff + (wid >> 1) * 16384;
#pragma unroll
        for (int mt = 0; mt < 4; mt++)
#pragma unroll
            for (int nt = 0; nt < 4; nt++) {
                int kl = nt * 8 + q2;
                int r0 = wm + mt * 16 + (lane >> 2);
                uint32_t w0 = (uint32_t)(r0 * 32 + (((kl >> 2) ^ (r0 & 7)) << 2) + (kl & 3));
                *(float2*)(smem + (pchunk - sb) + 4u * w0) =
                    make_float2(tf32_rna_f(Sacc[mt][nt][0]), tf32_rna_f(Sacc[mt][nt][1]));
                int r1 = r0 + 8;
                uint32_t w1 = (uint32_t)(r1 * 32 + (((kl >> 2) ^ (r1 & 7)) << 2) + (kl & 3));
                *(float2*)(smem + (pchunk - sb) + 4u * w1) =
                    make_float2(tf32_rna_f(Sacc[mt][nt][2]), tf32_rna_f(Sacc[mt][nt][3]));
            }
        __syncthreads();

        // finish l update
#pragma unroll
        for (int mt = 0; mt < 4; mt++)
#pragma unroll
            for (int hh = 0; hh < 2; hh++) {
                int row = wm + mt * 16 + hh * 8 + (lane >> 2);
                float s4 = redS[row * 4] + redS[row * 4 + 1] + redS[row * 4 + 2] + redS[row * 4 + 3];
                l_r[mt][hh] = l_r[mt][hh] * alpha[mt][hh] + s4;
                m_r[mt][hh] = mnew[mt][hh];
            }

        // ---- O += P @ V_blk ----
        const float* Vb = VT + (size_t)kvh * HD * S_LEN + kb * 128;
        fill_tile(sb + St0, Vb, S_LEN, tid);
        CP_COMMIT();
        for (int kc = 0; kc < 4; kc++) {
            if (kc < 3) {
                fill_tile(sb + St0 + ((kc + 1) & 1) * 16384, Vb + (kc + 1) * 32, S_LEN, tid);
                CP_COMMIT();
                CP_WAIT1();
            } else CP_WAIT0();
            __syncthreads();
            compute_tile(sb + Poff + kc * 16384, sb + St0 + (kc & 1) * 16384, Oacc, lane, wm, wn);
            __syncthreads();
        }
    }

    // ---- epilogue: O /= l, write rounded ----
#pragma unroll
    for (int mt = 0; mt < 4; mt++)
#pragma unroll
        for (int hh = 0; hh < 2; hh++) {
            float inv = 1.0f / l_r[mt][hh];
            int row = n * 128 + wm + mt * 16 + hh * 8 + (lane >> 2);
#pragma unroll
            for (int nt = 0; nt < 4; nt++) {
                int col = h * HD + wn + nt * 8 + q2;
                float2 v = make_float2(tf32_rna_f(Oacc[mt][nt][hh * 2] * inv),
                                       tf32_rna_f(Oacc[mt][nt][hh * 2 + 1] * inv));
                *(float2*)(O + (size_t)row * (NH * HD) + col) = v;
            }
        }
}

// ---------------- transpose + round: dst[C][R] = tf32(src[R][C]) ----------
__global__ void transpose_kernel(const float* __restrict__ src, float* __restrict__ dst,
                                 int R, int C) {
    __shared__ float t[32][33];
    int bx = blockIdx.x * 32, by = blockIdx.y * 32;
    int x = bx + threadIdx.x;
#pragma unroll
    for (int i = 0; i < 32; i += 8) {
        int y = by + threadIdx.y + i;
        t[threadIdx.y + i][threadIdx.x] = src[(size_t)y * C + x];
    }
    __syncthreads();
    int x2 = by + threadIdx.x;
#pragma unroll
    for (int i = 0; i < 32; i += 8) {
        int y2 = bx + threadIdx.y + i;
        dst[(size_t)y2 * R + x2] = tf32_rna_f(t[threadIdx.x][threadIdx.y + i]);
    }
}

// ---------------- elementwise tf32 round ----------------------------------
__global__ void round_kernel(const float* __restrict__ src, float* __restrict__ dst, int n4) {
    int i = blockIdx.x * blockDim.x + threadIdx.x;
    if (i >= n4) return;
    float4 v = ((const float4*)src)[i];
    v.x = tf32_rna_f(v.x); v.y = tf32_rna_f(v.y);
    v.z = tf32_rna_f(v.z); v.w = tf32_rna_f(v.w);
    ((float4*)dst)[i] = v;
}

// ---------------- RoPE (+round, + optional scale) -------------------------
__global__ void rope_kernel(float* __restrict__ X,
                            const float* __restrict__ cosb,
                            const float* __restrict__ sinb,
                            int nheads, float scale) {
    int idx = blockIdx.x * blockDim.x + threadIdx.x;
    int total = S_LEN * nheads * 64;
    if (idx >= total) return;
    int d = idx & 63;
    int hh = (idx >> 6) % nheads;
    int s = idx / (64 * nheads);
    float c1 = cosb[s * HD + d],      s1 = sinb[s * HD + d];
    float c2 = cosb[s * HD + d + 64], s2 = sinb[s * HD + d + 64];
    float* p = X + (size_t)s * (nheads * HD) + hh * HD + d;
    float x1 = p[0], x2 = p[64];
    p[0]  = tf32_rna_f((x1 * c1 - x2 * s1) * scale);
    p[64] = tf32_rna_f((x2 * c2 + x1 * s2) * scale);
}

// ---------------- launch --------------------------------------------------
extern "C" void kernel_launch(void* const* d_in, const int* in_sizes, int n_in,
                              void* d_out, int out_size) {
    const float* H    = (const float*)d_in[0];
    const float* mask = (const float*)d_in[1];
    const float* cosb = (const float*)d_in[2];
    const float* sinb = (const float*)d_in[3];
    const float* Wq   = (const float*)d_in[4];
    const float* Wk   = (const float*)d_in[5];
    const float* Wv   = (const float*)d_in[6];
    const float* Wo   = (const float*)d_in[7];
    float* out = (float*)d_out;

    float *Hr, *Qs, *Ks, *Vs, *Os, *WqT, *WkT, *WvT, *WoT, *VTs;
    cudaGetSymbolAddress((void**)&Hr, g_Hr);
    cudaGetSymbolAddress((void**)&Qs, g_Q);
    cudaGetSymbolAddress((void**)&Ks, g_K);
    cudaGetSymbolAddress((void**)&Vs, g_V);
    cudaGetSymbolAddress((void**)&Os, g_O);
    cudaGetSymbolAddress((void**)&WqT, g_WqT);
    cudaGetSymbolAddress((void**)&WkT, g_WkT);
    cudaGetSymbolAddress((void**)&WvT, g_WvT);
    cudaGetSymbolAddress((void**)&WoT, g_WoT);
    cudaGetSymbolAddress((void**)&VTs, g_VT);

    cudaFuncSetAttribute(gemm_tc_kernel, cudaFuncAttributeMaxDynamicSharedMemorySize, GEMM_SMEM);
    cudaFuncSetAttribute(flash_kernel,   cudaFuncAttributeMaxDynamicSharedMemorySize, FL_SMEM);

    dim3 tb(32, 8);
    round_kernel<<<(S_LEN * HID / 4 + 255) / 256, 256>>>(H, Hr, S_LEN * HID / 4);
    transpose_kernel<<<dim3(64, 64), tb>>>(Wq, WqT, HID, NH * HD);
    transpose_kernel<<<dim3(16, 64), tb>>>(Wk, WkT, HID, NKV * HD);
    transpose_kernel<<<dim3(16, 64), tb>>>(Wv, WvT, HID, NKV * HD);
    transpose_kernel<<<dim3(64, 64), tb>>>(Wo, WoT, NH * HD, HID);

    gemm_tc_kernel<<<dim3(16, 32), 256, GEMM_SMEM>>>(Hr, WqT, Qs, HID, NH * HD);
    gemm_tc_kernel<<<dim3(4, 32), 256, GEMM_SMEM>>>(Hr, WkT, Ks, HID, NKV * HD);
    gemm_tc_kernel<<<dim3(4, 32), 256, GEMM_SMEM>>>(Hr, WvT, Vs, HID, NKV * HD);

    rope_kernel<<<(S_LEN * NH * 64 + 255) / 256, 256>>>(Qs, cosb, sinb, NH, SCALE);
    rope_kernel<<<(S_LEN * NKV * 64 + 255) / 256, 256>>>(Ks, cosb, sinb, NKV, 1.0f);

    transpose_kernel<<<dim3(16, 128), tb>>>(Vs, VTs, S_LEN, NKV * HD);

    flash_kernel<<<dim3(NBLK, NH), 256, FL_SMEM>>>(Qs, Ks, VTs, mask, Os);

    gemm_tc_kernel<<<dim3(16, 32), 256, GEMM_SMEM>>>(Os, WoT, out, NH * HD, HID);
}

// round 7
// speedup vs baseline: 7.6351x; 1.7190x over previous
#include <cuda_runtime.h>
#include <cuda_fp16.h>
#include <cstdint>

#define S_LEN 4096
#define HID   2048
#define NH    16
#define NKV   4
#define HD    128
#define NBLK  32
#define NEGV  -1000000000.0f
#define SCALE 0.08838834764831845f   // HD^-0.5

// ---------------- scratch (half operands) ----------------
__device__ __half g_Hh[S_LEN * HID];
__device__ __half g_Qh[S_LEN * NH * HD];
__device__ __half g_Kh[S_LEN * NKV * HD];
__device__ __half g_Vh[S_LEN * NKV * HD];
__device__ __half g_VTh[(size_t)NKV * HD * S_LEN];
__device__ __half g_Oh[S_LEN * NH * HD];
__device__ __half g_WqTh[HID * NH * HD];
__device__ __half g_WkTh[HID * NKV * HD];
__device__ __half g_WvTh[HID * NKV * HD];
__device__ __half g_WoTh[(size_t)NH * HD * HID];

// ---------------- helpers ----------------
__device__ __forceinline__ uint32_t smem_u32(const void* p) {
    uint32_t a;
    asm("{ .reg .u64 t; cvta.to.shared.u64 t, %1; cvt.u32.u64 %0, t; }" : "=r"(a) : "l"(p));
    return a;
}
__device__ __forceinline__ void cp16(uint32_t dst, const void* src) {
    asm volatile("cp.async.cg.shared.global [%0], [%1], 16;" :: "r"(dst), "l"(src));
}
#define CP_COMMIT() asm volatile("cp.async.commit_group;" ::: "memory")
#define CP_WAIT1()  asm volatile("cp.async.wait_group 1;" ::: "memory")
#define CP_WAIT0()  asm volatile("cp.async.wait_group 0;" ::: "memory")

__device__ __forceinline__ void mma_f16(float c[4], const uint32_t a[4],
                                        uint32_t b0, uint32_t b1) {
    asm volatile(
        "mma.sync.aligned.m16n8k16.row.col.f32.f16.f16.f32 "
        "{%0,%1,%2,%3}, {%4,%5,%6,%7}, {%8,%9}, {%0,%1,%2,%3};"
        : "+f"(c[0]), "+f"(c[1]), "+f"(c[2]), "+f"(c[3])
        : "r"(a[0]), "r"(a[1]), "r"(a[2]), "r"(a[3]), "r"(b0), "r"(b1));
}
__device__ __forceinline__ void ldm_x4(uint32_t r[4], uint32_t addr) {
    asm volatile("ldmatrix.sync.aligned.m8n8.x4.shared.b16 {%0,%1,%2,%3}, [%4];"
                 : "=r"(r[0]), "=r"(r[1]), "=r"(r[2]), "=r"(r[3]) : "r"(addr));
}

// ---------------- key-block schedule ----------------
__device__ __forceinline__ int key_block(int n, int j, bool* valid) {
    if (j < 4) {
        int kb = n - 3 + j;
        *valid = (kb >= 0);
        return kb < 0 ? 0 : kb;
    }
    int jj = j - 4;
    if (jj == 0) { *valid = true; return 0; }
    int off = (4 - jj) * 8;
    int kb = n - off; if (kb < 0) kb = 0;
    int kprev;
    if (jj == 1) kprev = 0;
    else { int po = (5 - jj) * 8; kprev = n - po; if (kprev < 0) kprev = 0; }
    *valid = (kb != kprev);
    return kb;
}

// ---------------- smem tile: 128 rows x 64 halfs (128B), XOR swizzled -----
// 16B chunk c8 in row r stored at chunk (c8 ^ (r&7)); tile = 16 KB
__device__ __forceinline__ void fill_tile(uint32_t st, const __half* src, int stride, int tid) {
#pragma unroll
    for (int i = 0; i < 4; i++) {
        int idx = tid + i * 256;
        int r = idx >> 3, c8 = idx & 7;
        cp16(st + (uint32_t)((r << 3) + (c8 ^ (r & 7))) * 16,
             src + (size_t)r * stride + c8 * 8);
    }
}

// ---------------- fp16 128x128x64 compute (per call: one K64 chunk) -------
__device__ __forceinline__ void compute_tile(uint32_t aB, uint32_t bB,
                                             float acc[4][4][4],
                                             int lane, int wm, int wn) {
    int g = lane >> 3, l7 = lane & 7;
    int aRow = ((g & 1) << 3) + l7, aKc = g >> 1;
    int bRow = ((g >> 1) << 3) + l7, bKc = g & 1;
#pragma unroll
    for (int ks = 0; ks < 4; ks++) {
        uint32_t a[4][4], b[2][4];
#pragma unroll
        for (int mt = 0; mt < 4; mt++) {
            int r = wm + mt * 16 + aRow;
            int kc = ks * 2 + aKc;
            ldm_x4(a[mt], aB + (uint32_t)(r * 128 + ((kc ^ (r & 7)) << 4)));
        }
#pragma unroll
        for (int np = 0; np < 2; np++) {
            int r = wn + np * 16 + bRow;
            int kc = ks * 2 + bKc;
            ldm_x4(b[np], bB + (uint32_t)(r * 128 + ((kc ^ (r & 7)) << 4)));
        }
#pragma unroll
        for (int mt = 0; mt < 4; mt++)
#pragma unroll
            for (int np = 0; np < 2; np++) {
                mma_f16(acc[mt][np * 2],     a[mt], b[np][0], b[np][1]);
                mma_f16(acc[mt][np * 2 + 1], a[mt], b[np][2], b[np][3]);
            }
    }
}

// ---------------- generic GEMM: C[M,N] = A[M,K] @ BT[N,K]^T ---------------
#define GEMM_SMEM 65536
template <bool HALF_OUT>
__global__ void __launch_bounds__(256) gemm_h_kernel(const __half* __restrict__ A,
                                                     const __half* __restrict__ BT,
                                                     void* __restrict__ Cv,
                                                     int K, int N) {
    extern __shared__ char smem[];
    uint32_t sb = smem_u32(smem);
    int tid = threadIdx.x, lane = tid & 31, wid = tid >> 5;
    int wm = (wid & 1) * 64, wn = (wid >> 1) * 32;
    float acc[4][4][4];
#pragma unroll
    for (int mt = 0; mt < 4; mt++)
#pragma unroll
        for (int nt = 0; nt < 4; nt++)
#pragma unroll
            for (int c = 0; c < 4; c++) acc[mt][nt][c] = 0.f;

    const __half* Ab = A + (size_t)(blockIdx.y * 128) * K;
    const __half* Bb = BT + (size_t)(blockIdx.x * 128) * K;
    int nch = K / 64;
    fill_tile(sb, Ab, K, tid);
    fill_tile(sb + 16384, Bb, K, tid);
    CP_COMMIT();
    for (int kc = 0; kc < nch; kc++) {
        int s = kc & 1;
        if (kc + 1 < nch) {
            uint32_t st = sb + (s ^ 1) * 32768;
            fill_tile(st, Ab + (kc + 1) * 64, K, tid);
            fill_tile(st + 16384, Bb + (kc + 1) * 64, K, tid);
            CP_COMMIT();
            CP_WAIT1();
        } else CP_WAIT0();
        __syncthreads();
        compute_tile(sb + s * 32768, sb + s * 32768 + 16384, acc, lane, wm, wn);
        __syncthreads();
    }
    int row0 = blockIdx.y * 128 + wm + (lane >> 2);
    int col0 = blockIdx.x * 128 + wn + 2 * (lane & 3);
    if (HALF_OUT) {
        __half* C = (__half*)Cv;
#pragma unroll
        for (int mt = 0; mt < 4; mt++)
#pragma unroll
            for (int nt = 0; nt < 4; nt++) {
                __half* p = C + (size_t)(row0 + mt * 16) * N + col0 + nt * 8;
                *(__half2*)p = __floats2half2_rn(acc[mt][nt][0], acc[mt][nt][1]);
                *(__half2*)(p + 8 * (size_t)N) = __floats2half2_rn(acc[mt][nt][2], acc[mt][nt][3]);
            }
    } else {
        float* C = (float*)Cv;
#pragma unroll
        for (int mt = 0; mt < 4; mt++)
#pragma unroll
            for (int nt = 0; nt < 4; nt++) {
                float* p = C + (size_t)(row0 + mt * 16) * N + col0 + nt * 8;
                *(float2*)p = make_float2(acc[mt][nt][0], acc[mt][nt][1]);
                *(float2*)(p + 8 * (size_t)N) = make_float2(acc[mt][nt][2], acc[mt][nt][3]);
            }
    }
}

// ---------------- fused flash attention -----------------------------------
// smem: Q 2x16K | P 2x16K | stage 2x16K | redM 2K | redS 2K = 102400 B
#define FL_SMEM 102400
__global__ void __launch_bounds__(256, 1) flash_kernel(const __half* __restrict__ Q,
                                                       const __half* __restrict__ Kmat,
                                                       const __half* __restrict__ VT,
                                                       const float* __restrict__ mask,
                                                       __half* __restrict__ O) {
    int n = blockIdx.x, h = blockIdx.y, kvh = h >> 2;
    extern __shared__ char smem[];
    uint32_t sb = smem_u32(smem);
    const uint32_t Qoff = 0, Poff = 32768, St0 = 65536, St1 = 81920;
    float* redM = (float*)(smem + 98304);
    float* redS = (float*)(smem + 100352);
    int tid = threadIdx.x, lane = tid & 31, wid = tid >> 5;
    int wm = (wid & 1) * 64, wn = (wid >> 1) * 32;
    int q2 = 2 * (lane & 3);

    const __half* Qb = Q + (size_t)(n * 128) * (NH * HD) + h * HD;
    fill_tile(sb + Qoff, Qb, NH * HD, tid);
    fill_tile(sb + Qoff + 16384, Qb + 64, NH * HD, tid);
    CP_COMMIT();
    CP_WAIT0();
    __syncthreads();

    float Oacc[4][4][4];
#pragma unroll
    for (int mt = 0; mt < 4; mt++)
#pragma unroll
        for (int nt = 0; nt < 4; nt++)
#pragma unroll
            for (int c = 0; c < 4; c++) Oacc[mt][nt][c] = 0.f;
    float m_r[4][2], l_r[4][2];
#pragma unroll
    for (int mt = 0; mt < 4; mt++) { m_r[mt][0] = m_r[mt][1] = -1e30f; l_r[mt][0] = l_r[mt][1] = 0.f; }

    for (int j = 0; j < 8; j++) {
        bool valid; int kb = key_block(n, j, &valid);
        if (!valid) continue;

        const __half* Kb = Kmat + (size_t)(kb * 128) * (NKV * HD) + kvh * HD;
        const __half* Vb = VT + (size_t)kvh * HD * S_LEN + kb * 128;

        // ---- S = Q @ K_blk^T (2 chunks of K64), prefetch V behind ----
        float Sacc[4][4][4];
#pragma unroll
        for (int mt = 0; mt < 4; mt++)
#pragma unroll
            for (int nt = 0; nt < 4; nt++)
#pragma unroll
                for (int c = 0; c < 4; c++) Sacc[mt][nt][c] = 0.f;

        fill_tile(sb + St0, Kb, NKV * HD, tid);
        CP_COMMIT();
        fill_tile(sb + St1, Kb + 64, NKV * HD, tid);
        CP_COMMIT();
        CP_WAIT1();
        __syncthreads();
        compute_tile(sb + Qoff, sb + St0, Sacc, lane, wm, wn);
        __syncthreads();
        fill_tile(sb + St0, Vb, S_LEN, tid);        // V key-cols 0-63 into slot0
        CP_COMMIT();
        CP_WAIT1();                                  // K chunk1 ready
        __syncthreads();
        compute_tile(sb + Qoff + 16384, sb + St1, Sacc, lane, wm, wn);
        __syncthreads();
        fill_tile(sb + St1, Vb + 64, S_LEN, tid);    // V key-cols 64-127 (FIX)
        CP_COMMIT();

        // ---- bias: mask + causal (j==3) ----
        const float* mrow = mask + kb * 128;
#pragma unroll
        for (int nt = 0; nt < 4; nt++) {
            int s0 = wn + nt * 8 + q2;
            float b0 = (1.0f - mrow[s0]) * NEGV;
            float b1 = (1.0f - mrow[s0 + 1]) * NEGV;
#pragma unroll
            for (int mt = 0; mt < 4; mt++) {
                Sacc[mt][nt][0] += b0; Sacc[mt][nt][1] += b1;
                Sacc[mt][nt][2] += b0; Sacc[mt][nt][3] += b1;
            }
            if (j == 3) {
#pragma unroll
                for (int mt = 0; mt < 4; mt++) {
                    int t0 = wm + mt * 16 + (lane >> 2);
                    if (s0 > t0) Sacc[mt][nt][0] += NEGV;
                    if (s0 + 1 > t0) Sacc[mt][nt][1] += NEGV;
                    if (s0 > t0 + 8) Sacc[mt][nt][2] += NEGV;
                    if (s0 + 1 > t0 + 8) Sacc[mt][nt][3] += NEGV;
                }
            }
        }

        // ---- block row-max ----
        float bm[4][2];
#pragma unroll
        for (int mt = 0; mt < 4; mt++) {
            float v0 = -1e30f, v1 = -1e30f;
#pragma unroll
            for (int nt = 0; nt < 4; nt++) {
                v0 = fmaxf(v0, fmaxf(Sacc[mt][nt][0], Sacc[mt][nt][1]));
                v1 = fmaxf(v1, fmaxf(Sacc[mt][nt][2], Sacc[mt][nt][3]));
            }
            v0 = fmaxf(v0, __shfl_xor_sync(0xffffffffu, v0, 1));
            v0 = fmaxf(v0, __shfl_xor_sync(0xffffffffu, v0, 2));
            v1 = fmaxf(v1, __shfl_xor_sync(0xffffffffu, v1, 1));
            v1 = fmaxf(v1, __shfl_xor_sync(0xffffffffu, v1, 2));
            bm[mt][0] = v0; bm[mt][1] = v1;
        }
        if ((lane & 3) == 0) {
#pragma unroll
            for (int mt = 0; mt < 4; mt++)
#pragma unroll
                for (int hh = 0; hh < 2; hh++) {
                    int row = wm + mt * 16 + hh * 8 + (lane >> 2);
                    redM[row * 4 + (wid >> 1)] = bm[mt][hh];
                }
        }
        __syncthreads();

        float mnew[4][2], alpha[4][2];
#pragma unroll
        for (int mt = 0; mt < 4; mt++)
#pragma unroll
            for (int hh = 0; hh < 2; hh++) {
                int row = wm + mt * 16 + hh * 8 + (lane >> 2);
                float g = fmaxf(fmaxf(redM[row * 4], redM[row * 4 + 1]),
                                fmaxf(redM[row * 4 + 2], redM[row * 4 + 3]));
                g = fmaxf(g, m_r[mt][hh]);
                alpha[mt][hh] = __expf(m_r[mt][hh] - g);
                mnew[mt][hh] = g;
            }

        // ---- P = exp(S - m), rescale O, partial sums ----
        float ps[4][2];
#pragma unroll
        for (int mt = 0; mt < 4; mt++) { ps[mt][0] = 0.f; ps[mt][1] = 0.f; }
#pragma unroll
        for (int mt = 0; mt < 4; mt++)
#pragma unroll
            for (int nt = 0; nt < 4; nt++) {
                float p0 = __expf(Sacc[mt][nt][0] - mnew[mt][0]);
                float p1 = __expf(Sacc[mt][nt][1] - mnew[mt][0]);
                float p2 = __expf(Sacc[mt][nt][2] - mnew[mt][1]);
                float p3 = __expf(Sacc[mt][nt][3] - mnew[mt][1]);
                Sacc[mt][nt][0] = p0; Sacc[mt][nt][1] = p1;
                Sacc[mt][nt][2] = p2; Sacc[mt][nt][3] = p3;
                ps[mt][0] += p0 + p1; ps[mt][1] += p2 + p3;
                Oacc[mt][nt][0] *= alpha[mt][0]; Oacc[mt][nt][1] *= alpha[mt][0];
                Oacc[mt][nt][2] *= alpha[mt][1]; Oacc[mt][nt][3] *= alpha[mt][1];
            }
#pragma unroll
        for (int mt = 0; mt < 4; mt++)
#pragma unroll
            for (int hh = 0; hh < 2; hh++) {
                float v = ps[mt][hh];
                v += __shfl_xor_sync(0xffffffffu, v, 1);
                v += __shfl_xor_sync(0xffffffffu, v, 2);
                ps[mt][hh] = v;
            }
        if ((lane & 3) == 0) {
#pragma unroll
            for (int mt = 0; mt < 4; mt++)
#pragma unroll
                for (int hh = 0; hh < 2; hh++) {
                    int row = wm + mt * 16 + hh * 8 + (lane >> 2);
                    redS[row * 4 + (wid >> 1)] = ps[mt][hh];
                }
        }

        // ---- store P to smem as half (chunk = key cols 0-63 / 64-127) ----
        uint32_t pbase = Poff + ((wn >= 64) ? 16384u : 0u);
        int klc = (wn & 63);
#pragma unroll
        for (int mt = 0; mt < 4; mt++)
#pragma unroll
            for (int nt = 0; nt < 4; nt++) {
                int kc = klc + nt * 8 + q2;
                int r0 = wm + mt * 16 + (lane >> 2);
                uint32_t b0 = (uint32_t)(r0 * 128 + (((kc >> 3) ^ (r0 & 7)) << 4) + (kc & 7) * 2);
                *(__half2*)(smem + pbase + b0) = __floats2half2_rn(Sacc[mt][nt][0], Sacc[mt][nt][1]);
                int r1 = r0 + 8;
                uint32_t b1 = (uint32_t)(r1 * 128 + (((kc >> 3) ^ (r1 & 7)) << 4) + (kc & 7) * 2);
                *(__half2*)(smem + pbase + b1) = __floats2half2_rn(Sacc[mt][nt][2], Sacc[mt][nt][3]);
            }
        __syncthreads();

        // finish l update
#pragma unroll
        for (int mt = 0; mt < 4; mt++)
#pragma unroll
            for (int hh = 0; hh < 2; hh++) {
                int row = wm + mt * 16 + hh * 8 + (lane >> 2);
                float s4 = redS[row * 4] + redS[row * 4 + 1] + redS[row * 4 + 2] + redS[row * 4 + 3];
                l_r[mt][hh] = l_r[mt][hh] * alpha[mt][hh] + s4;
                m_r[mt][hh] = mnew[mt][hh];
            }

        // ---- O += P @ V_blk (2 chunks; V prefetched above) ----
        CP_WAIT1();                                  // V chunk0 ready
        __syncthreads();
        compute_tile(sb + Poff, sb + St0, Oacc, lane, wm, wn);
        __syncthreads();
        CP_WAIT0();                                  // V chunk1 ready
        __syncthreads();
        compute_tile(sb + Poff + 16384, sb + St1, Oacc, lane, wm, wn);
        __syncthreads();
    }

    // ---- epilogue: O /= l, write half ----
#pragma unroll
    for (int mt = 0; mt < 4; mt++)
#pragma unroll
        for (int hh = 0; hh < 2; hh++) {
            float inv = 1.0f / l_r[mt][hh];
            int row = n * 128 + wm + mt * 16 + hh * 8 + (lane >> 2);
#pragma unroll
            for (int nt = 0; nt < 4; nt++) {
                int col = h * HD + wn + nt * 8 + q2;
                *(__half2*)(O + (size_t)row * (NH * HD) + col) =
                    __floats2half2_rn(Oacc[mt][nt][hh * 2] * inv, Oacc[mt][nt][hh * 2 + 1] * inv);
            }
        }
}

// ---------------- transpose float src -> half dst: dst[C][R] --------------
__global__ void transpose_f2h_kernel(const float* __restrict__ src, __half* __restrict__ dst,
                                     int R, int C) {
    __shared__ float t[32][33];
    int bx = blockIdx.x * 32, by = blockIdx.y * 32;
    int x = bx + threadIdx.x;
#pragma unroll
    for (int i = 0; i < 32; i += 8) {
        int y = by + threadIdx.y + i;
        t[threadIdx.y + i][threadIdx.x] = src[(size_t)y * C + x];
    }
    __syncthreads();
    int x2 = by + threadIdx.x;
#pragma unroll
    for (int i = 0; i < 32; i += 8) {
        int y2 = bx + threadIdx.y + i;
        dst[(size_t)y2 * R + x2] = __float2half_rn(t[threadIdx.x][threadIdx.y + i]);
    }
}

// ---------------- transpose half src -> half dst ---------------------------
__global__ void transpose_h2h_kernel(const __half* __restrict__ src, __half* __restrict__ dst,
                                     int R, int C) {
    __shared__ __half t[32][33];
    int bx = blockIdx.x * 32, by = blockIdx.y * 32;
    int x = bx + threadIdx.x;
#pragma unroll
    for (int i = 0; i < 32; i += 8) {
        int y = by + threadIdx.y + i;
        t[threadIdx.y + i][threadIdx.x] = src[(size_t)y * C + x];
    }
    __syncthreads();
    int x2 = by + threadIdx.x;
#pragma unroll
    for (int i = 0; i < 32; i += 8) {
        int y2 = bx + threadIdx.y + i;
        dst[(size_t)y2 * R + x2] = t[threadIdx.x][threadIdx.y + i];
    }
}

// ---------------- float -> half convert ------------------------------------
__global__ void f2h_kernel(const float* __restrict__ src, __half* __restrict__ dst, int n4) {
    int i = blockIdx.x * blockDim.x + threadIdx.x;
    if (i >= n4) return;
    float4 v = ((const float4*)src)[i];
    __half2 a = __floats2half2_rn(v.x, v.y);
    __half2 b = __floats2half2_rn(v.z, v.w);
    ((uint2*)dst)[i] = make_uint2(*(uint32_t*)&a, *(uint32_t*)&b);
}

// ---------------- RoPE on half (compute f32, + optional scale) -------------
__global__ void rope_h_kernel(__half* __restrict__ X,
                              const float* __restrict__ cosb,
                              const float* __restrict__ sinb,
                              int nheads, float scale) {
    int idx = blockIdx.x * blockDim.x + threadIdx.x;
    int total = S_LEN * nheads * 64;
    if (idx >= total) return;
    int d = idx & 63;
    int hh = (idx >> 6) % nheads;
    int s = idx / (64 * nheads);
    float c1 = cosb[s * HD + d],      s1 = sinb[s * HD + d];
    float c2 = cosb[s * HD + d + 64], s2 = sinb[s * HD + d + 64];
    __half* p = X + (size_t)s * (nheads * HD) + hh * HD + d;
    float x1 = __half2float(p[0]), x2 = __half2float(p[64]);
    p[0]  = __float2half_rn((x1 * c1 - x2 * s1) * scale);
    p[64] = __float2half_rn((x2 * c2 + x1 * s2) * scale);
}

// ---------------- launch --------------------------------------------------
extern "C" void kernel_launch(void* const* d_in, const int* in_sizes, int n_in,
                              void* d_out, int out_size) {
    const float* H    = (const float*)d_in[0];
    const float* mask = (const float*)d_in[1];
    const float* cosb = (const float*)d_in[2];
    const float* sinb = (const float*)d_in[3];
    const float* Wq   = (const float*)d_in[4];
    const float* Wk   = (const float*)d_in[5];
    const float* Wv   = (const float*)d_in[6];
    const float* Wo   = (const float*)d_in[7];
    float* out = (float*)d_out;

    __half *Hh, *Qh, *Kh, *Vh, *VTh, *Oh, *WqT, *WkT, *WvT, *WoT;
    cudaGetSymbolAddress((void**)&Hh, g_Hh);
    cudaGetSymbolAddress((void**)&Qh, g_Qh);
    cudaGetSymbolAddress((void**)&Kh, g_Kh);
    cudaGetSymbolAddress((void**)&Vh, g_Vh);
    cudaGetSymbolAddress((void**)&VTh, g_VTh);
    cudaGetSymbolAddress((void**)&Oh, g_Oh);
    cudaGetSymbolAddress((void**)&WqT, g_WqTh);
    cudaGetSymbolAddress((void**)&WkT, g_WkTh);
    cudaGetSymbolAddress((void**)&WvT, g_WvTh);
    cudaGetSymbolAddress((void**)&WoT, g_WoTh);

    cudaFuncSetAttribute(gemm_h_kernel<true>,  cudaFuncAttributeMaxDynamicSharedMemorySize, GEMM_SMEM);
    cudaFuncSetAttribute(gemm_h_kernel<false>, cudaFuncAttributeMaxDynamicSharedMemorySize, GEMM_SMEM);
    cudaFuncSetAttribute(flash_kernel,         cudaFuncAttributeMaxDynamicSharedMemorySize, FL_SMEM);

    dim3 tb(32, 8);
    f2h_kernel<<<(S_LEN * HID / 4 + 255) / 256, 256>>>(H, Hh, S_LEN * HID / 4);
    transpose_f2h_kernel<<<dim3(64, 64), tb>>>(Wq, WqT, HID, NH * HD);
    transpose_f2h_kernel<<<dim3(16, 64), tb>>>(Wk, WkT, HID, NKV * HD);
    transpose_f2h_kernel<<<dim3(16, 64), tb>>>(Wv, WvT, HID, NKV * HD);
    transpose_f2h_kernel<<<dim3(64, 64), tb>>>(Wo, WoT, NH * HD, HID);

    gemm_h_kernel<true><<<dim3(16, 32), 256, GEMM_SMEM>>>(Hh, WqT, Qh, HID, NH * HD);
    gemm_h_kernel<true><<<dim3(4, 32), 256, GEMM_SMEM>>>(Hh, WkT, Kh, HID, NKV * HD);
    gemm_h_kernel<true><<<dim3(4, 32), 256, GEMM_SMEM>>>(Hh, WvT, Vh, HID, NKV * HD);

    rope_h_kernel<<<(S_LEN * NH * 64 + 255) / 256, 256>>>(Qh, cosb, sinb, NH, SCALE);
    rope_h_kernel<<<(S_LEN * NKV * 64 + 255) / 256, 256>>>(Kh, cosb, sinb, NKV, 1.0f);

    transpose_h2h_kernel<<<dim3(16, 128), tb>>>(Vh, VTh, S_LEN, NKV * HD);

    flash_kernel<<<dim3(NBLK, NH), 256, FL_SMEM>>>(Qh, Kh, VTh, mask, Oh);

    gemm_h_kernel<false><<<dim3(16, 32), 256, GEMM_SMEM>>>(Oh, WoT, out, NH * HD, HID);
}

// round 9
// speedup vs baseline: 7.9599x; 1.0425x over previous
#include <cuda_runtime.h>
#include <cuda_fp16.h>
#include <cstdint>

#define S_LEN 4096
#define HID   2048
#define NH    16
#define NKV   4
#define HD    128
#define NBLK  32
#define QKV_N 3072          // NH*HD + 2*NKV*HD
#define NEGV  -1000000000.0f
#define SCALE 0.08838834764831845f   // HD^-0.5

// ---------------- scratch (half operands) ----------------
__device__ __half g_Hh[S_LEN * HID];
__device__ __half g_QKVh[(size_t)S_LEN * QKV_N];          // Q | K | V column slices
__device__ __half g_VTh[(size_t)NKV * HD * S_LEN];
__device__ __half g_Oh[S_LEN * NH * HD];
__device__ __half g_WqkvT[(size_t)QKV_N * HID];           // [WqT;WkT;WvT] rows
__device__ __half g_WoTh[(size_t)NH * HD * HID];

// ---------------- helpers ----------------
__device__ __forceinline__ uint32_t smem_u32(const void* p) {
    uint32_t a;
    asm("{ .reg .u64 t; cvta.to.shared.u64 t, %1; cvt.u32.u64 %0, t; }" : "=r"(a) : "l"(p));
    return a;
}
__device__ __forceinline__ void cp16(uint32_t dst, const void* src) {
    asm volatile("cp.async.cg.shared.global [%0], [%1], 16;" :: "r"(dst), "l"(src));
}
#define CP_COMMIT() asm volatile("cp.async.commit_group;" ::: "memory")
#define CP_WAIT0()  asm volatile("cp.async.wait_group 0;" ::: "memory")
#define CP_WAIT1()  asm volatile("cp.async.wait_group 1;" ::: "memory")
#define CP_WAIT2()  asm volatile("cp.async.wait_group 2;" ::: "memory")
#define CP_WAIT3()  asm volatile("cp.async.wait_group 3;" ::: "memory")

__device__ __forceinline__ void mma_f16(float c[4], const uint32_t a[4],
                                        uint32_t b0, uint32_t b1) {
    asm volatile(
        "mma.sync.aligned.m16n8k16.row.col.f32.f16.f16.f32 "
        "{%0,%1,%2,%3}, {%4,%5,%6,%7}, {%8,%9}, {%0,%1,%2,%3};"
        : "+f"(c[0]), "+f"(c[1]), "+f"(c[2]), "+f"(c[3])
        : "r"(a[0]), "r"(a[1]), "r"(a[2]), "r"(a[3]), "r"(b0), "r"(b1));
}
__device__ __forceinline__ void ldm_x4(uint32_t r[4], uint32_t addr) {
    asm volatile("ldmatrix.sync.aligned.m8n8.x4.shared.b16 {%0,%1,%2,%3}, [%4];"
                 : "=r"(r[0]), "=r"(r[1]), "=r"(r[2]), "=r"(r[3]) : "r"(addr));
}

// ---------------- key-block schedule ----------------
__device__ __forceinline__ int key_block(int n, int j, bool* valid) {
    if (j < 4) {
        int kb = n - 3 + j;
        *valid = (kb >= 0);
        return kb < 0 ? 0 : kb;
    }
    int jj = j - 4;
    if (jj == 0) { *valid = true; return 0; }
    int off = (4 - jj) * 8;
    int kb = n - off; if (kb < 0) kb = 0;
    int kprev;
    if (jj == 1) kprev = 0;
    else { int po = (5 - jj) * 8; kprev = n - po; if (kprev < 0) kprev = 0; }
    *valid = (kb != kprev);
    return kb;
}

// ---------------- smem tile: 128 rows x 64 halfs (128B), XOR swizzled -----
__device__ __forceinline__ void fill_tile(uint32_t st, const __half* src, int stride, int tid) {
#pragma unroll
    for (int i = 0; i < 4; i++) {
        int idx = tid + i * 256;
        int r = idx >> 3, c8 = idx & 7;
        cp16(st + (uint32_t)((r << 3) + (c8 ^ (r & 7))) * 16,
             src + (size_t)r * stride + c8 * 8);
    }
}

// ---------------- fp16 128x128x64 compute (one K64 chunk) -----------------
__device__ __forceinline__ void compute_tile(uint32_t aB, uint32_t bB,
                                             float acc[4][4][4],
                                             int lane, int wm, int wn) {
    int g = lane >> 3, l7 = lane & 7;
    int aRow = ((g & 1) << 3) + l7, aKc = g >> 1;
    int bRow = ((g >> 1) << 3) + l7, bKc = g & 1;
#pragma unroll
    for (int ks = 0; ks < 4; ks++) {
        uint32_t a[4][4], b[2][4];
#pragma unroll
        for (int mt = 0; mt < 4; mt++) {
            int r = wm + mt * 16 + aRow;
            int kc = ks * 2 + aKc;
            ldm_x4(a[mt], aB + (uint32_t)(r * 128 + ((kc ^ (r & 7)) << 4)));
        }
#pragma unroll
        for (int np = 0; np < 2; np++) {
            int r = wn + np * 16 + bRow;
            int kc = ks * 2 + bKc;
            ldm_x4(b[np], bB + (uint32_t)(r * 128 + ((kc ^ (r & 7)) << 4)));
        }
#pragma unroll
        for (int mt = 0; mt < 4; mt++)
#pragma unroll
            for (int np = 0; np < 2; np++) {
                mma_f16(acc[mt][np * 2],     a[mt], b[np][0], b[np][1]);
                mma_f16(acc[mt][np * 2 + 1], a[mt], b[np][2], b[np][3]);
            }
    }
}

// ---------------- GEMM: C[M,N] = A[M,K] @ BT[N,K]^T, 3-stage pipeline -----
#define GEMM_SMEM 98304
template <bool HALF_OUT>
__global__ void __launch_bounds__(256) gemm_h_kernel(const __half* __restrict__ A,
                                                     const __half* __restrict__ BT,
                                                     void* __restrict__ Cv,
                                                     int K, int N) {
    extern __shared__ char smem[];
    uint32_t sb = smem_u32(smem);
    int tid = threadIdx.x, lane = tid & 31, wid = tid >> 5;
    int wm = (wid & 1) * 64, wn = (wid >> 1) * 32;
    float acc[4][4][4];
#pragma unroll
    for (int mt = 0; mt < 4; mt++)
#pragma unroll
        for (int nt = 0; nt < 4; nt++)
#pragma unroll
            for (int c = 0; c < 4; c++) acc[mt][nt][c] = 0.f;

    const __half* Ab = A + (size_t)(blockIdx.y * 128) * K;
    const __half* Bb = BT + (size_t)(blockIdx.x * 128) * K;
    int nch = K / 64;
    // prologue: stages 0 and 1
    fill_tile(sb, Ab, K, tid);
    fill_tile(sb + 16384, Bb, K, tid);
    CP_COMMIT();
    fill_tile(sb + 32768, Ab + 64, K, tid);
    fill_tile(sb + 32768 + 16384, Bb + 64, K, tid);
    CP_COMMIT();

    int s = 0, nf = 2;
    for (int kc = 0; kc < nch; kc++) {
        if (kc + 1 < nch) CP_WAIT1(); else CP_WAIT0();
        __syncthreads();
        if (kc + 2 < nch) {
            uint32_t st = sb + nf * 32768;
            fill_tile(st, Ab + (kc + 2) * 64, K, tid);
            fill_tile(st + 16384, Bb + (kc + 2) * 64, K, tid);
            CP_COMMIT();
            nf = (nf == 2) ? 0 : nf + 1;
        }
        compute_tile(sb + s * 32768, sb + s * 32768 + 16384, acc, lane, wm, wn);
        s = (s == 2) ? 0 : s + 1;
    }
    int row0 = blockIdx.y * 128 + wm + (lane >> 2);
    int col0 = blockIdx.x * 128 + wn + 2 * (lane & 3);
    if (HALF_OUT) {
        __half* C = (__half*)Cv;
#pragma unroll
        for (int mt = 0; mt < 4; mt++)
#pragma unroll
            for (int nt = 0; nt < 4; nt++) {
                __half* p = C + (size_t)(row0 + mt * 16) * N + col0 + nt * 8;
                *(__half2*)p = __floats2half2_rn(acc[mt][nt][0], acc[mt][nt][1]);
                *(__half2*)(p + 8 * (size_t)N) = __floats2half2_rn(acc[mt][nt][2], acc[mt][nt][3]);
            }
    } else {
        float* C = (float*)Cv;
#pragma unroll
        for (int mt = 0; mt < 4; mt++)
#pragma unroll
            for (int nt = 0; nt < 4; nt++) {
                float* p = C + (size_t)(row0 + mt * 16) * N + col0 + nt * 8;
                *(float2*)p = make_float2(acc[mt][nt][0], acc[mt][nt][1]);
                *(float2*)(p + 8 * (size_t)N) = make_float2(acc[mt][nt][2], acc[mt][nt][3]);
            }
    }
}

// ---------------- fused flash attention -----------------------------------
// smem: Q 2x16K | P 2x16K | K0 K1 V0 V1 4x16K | redM 2K | redS 2K = 135168
#define FL_SMEM 135168
__global__ void __launch_bounds__(256, 1) flash_kernel(const __half* __restrict__ Q,
                                                       const __half* __restrict__ Kmat,
                                                       const __half* __restrict__ VT,
                                                       const float* __restrict__ mask,
                                                       __half* __restrict__ O) {
    int n = blockIdx.x, h = blockIdx.y, kvh = h >> 2;
    extern __shared__ char smem[];
    uint32_t sb = smem_u32(smem);
    const uint32_t Qoff = 0, Poff = 32768;
    const uint32_t SK0 = 65536, SK1 = 81920, SV0 = 98304, SV1 = 114688;
    float* redM = (float*)(smem + 131072);
    float* redS = (float*)(smem + 133120);
    int tid = threadIdx.x, lane = tid & 31, wid = tid >> 5;
    int wm = (wid & 1) * 64, wn = (wid >> 1) * 32;
    int q2 = 2 * (lane & 3);

    const __half* Qb = Q + (size_t)(n * 128) * QKV_N + h * HD;
    fill_tile(sb + Qoff, Qb, QKV_N, tid);
    fill_tile(sb + Qoff + 16384, Qb + 64, QKV_N, tid);
    CP_COMMIT();
    CP_WAIT0();
    __syncthreads();

    float Oacc[4][4][4];
#pragma unroll
    for (int mt = 0; mt < 4; mt++)
#pragma unroll
        for (int nt = 0; nt < 4; nt++)
#pragma unroll
            for (int c = 0; c < 4; c++) Oacc[mt][nt][c] = 0.f;
    float m_r[4][2], l_r[4][2];
#pragma unroll
    for (int mt = 0; mt < 4; mt++) { m_r[mt][0] = m_r[mt][1] = -1e30f; l_r[mt][0] = l_r[mt][1] = 0.f; }

    for (int j = 0; j < 8; j++) {
        bool valid; int kb = key_block(n, j, &valid);
        if (!valid) continue;

        const __half* Kb = Kmat + (size_t)(kb * 128) * QKV_N + kvh * HD;
        const __half* Vb = VT + (size_t)kvh * HD * S_LEN + kb * 128;

        // issue all 4 tile loads up front (4 commit groups)
        fill_tile(sb + SK0, Kb, QKV_N, tid);       CP_COMMIT();
        fill_tile(sb + SK1, Kb + 64, QKV_N, tid);  CP_COMMIT();
        fill_tile(sb + SV0, Vb, S_LEN, tid);       CP_COMMIT();
        fill_tile(sb + SV1, Vb + 64, S_LEN, tid);  CP_COMMIT();

        // ---- S = Q @ K_blk^T ----
        float Sacc[4][4][4];
#pragma unroll
        for (int mt = 0; mt < 4; mt++)
#pragma unroll
            for (int nt = 0; nt < 4; nt++)
#pragma unroll
                for (int c = 0; c < 4; c++) Sacc[mt][nt][c] = 0.f;

        CP_WAIT3();
        __syncthreads();
        compute_tile(sb + Qoff, sb + SK0, Sacc, lane, wm, wn);
        CP_WAIT2();
        __syncthreads();
        compute_tile(sb + Qoff + 16384, sb + SK1, Sacc, lane, wm, wn);

        // ---- bias: mask + causal (j==3) ----
        const float* mrow = mask + kb * 128;
#pragma unroll
        for (int nt = 0; nt < 4; nt++) {
            int s0 = wn + nt * 8 + q2;
            float b0 = (1.0f - mrow[s0]) * NEGV;
            float b1 = (1.0f - mrow[s0 + 1]) * NEGV;
#pragma unroll
            for (int mt = 0; mt < 4; mt++) {
                Sacc[mt][nt][0] += b0; Sacc[mt][nt][1] += b1;
                Sacc[mt][nt][2] += b0; Sacc[mt][nt][3] += b1;
            }
            if (j == 3) {
#pragma unroll
                for (int mt = 0; mt < 4; mt++) {
                    int t0 = wm + mt * 16 + (lane >> 2);
                    if (s0 > t0) Sacc[mt][nt][0] += NEGV;
                    if (s0 + 1 > t0) Sacc[mt][nt][1] += NEGV;
                    if (s0 > t0 + 8) Sacc[mt][nt][2] += NEGV;
                    if (s0 + 1 > t0 + 8) Sacc[mt][nt][3] += NEGV;
                }
            }
        }

        // ---- block row-max ----
        float bm[4][2];
#pragma unroll
        for (int mt = 0; mt < 4; mt++) {
            float v0 = -1e30f, v1 = -1e30f;
#pragma unroll
            for (int nt = 0; nt < 4; nt++) {
                v0 = fmaxf(v0, fmaxf(Sacc[mt][nt][0], Sacc[mt][nt][1]));
                v1 = fmaxf(v1, fmaxf(Sacc[mt][nt][2], Sacc[mt][nt][3]));
            }
            v0 = fmaxf(v0, __shfl_xor_sync(0xffffffffu, v0, 1));
            v0 = fmaxf(v0, __shfl_xor_sync(0xffffffffu, v0, 2));
            v1 = fmaxf(v1, __shfl_xor_sync(0xffffffffu, v1, 1));
            v1 = fmaxf(v1, __shfl_xor_sync(0xffffffffu, v1, 2));
            bm[mt][0] = v0; bm[mt][1] = v1;
        }
        if ((lane & 3) == 0) {
#pragma unroll
            for (int mt = 0; mt < 4; mt++)
#pragma unroll
                for (int hh = 0; hh < 2; hh++) {
                    int row = wm + mt * 16 + hh * 8 + (lane >> 2);
                    redM[row * 4 + (wid >> 1)] = bm[mt][hh];
                }
        }
        __syncthreads();

        float mnew[4][2], alpha[4][2];
#pragma unroll
        for (int mt = 0; mt < 4; mt++)
#pragma unroll
            for (int hh = 0; hh < 2; hh++) {
                int row = wm + mt * 16 + hh * 8 + (lane >> 2);
                float g = fmaxf(fmaxf(redM[row * 4], redM[row * 4 + 1]),
                                fmaxf(redM[row * 4 + 2], redM[row * 4 + 3]));
                g = fmaxf(g, m_r[mt][hh]);
                alpha[mt][hh] = __expf(m_r[mt][hh] - g);
                mnew[mt][hh] = g;
            }

        // ---- P = exp(S - m), rescale O, partial sums ----
        float ps[4][2];
#pragma unroll
        for (int mt = 0; mt < 4; mt++) { ps[mt][0] = 0.f; ps[mt][1] = 0.f; }
#pragma unroll
        for (int mt = 0; mt < 4; mt++)
#pragma unroll
            for (int nt = 0; nt < 4; nt++) {
                float p0 = __expf(Sacc[mt][nt][0] - mnew[mt][0]);
                float p1 = __expf(Sacc[mt][nt][1] - mnew[mt][0]);
                float p2 = __expf(Sacc[mt][nt][2] - mnew[mt][1]);
                float p3 = __expf(Sacc[mt][nt][3] - mnew[mt][1]);
                Sacc[mt][nt][0] = p0; Sacc[mt][nt][1] = p1;
                Sacc[mt][nt][2] = p2; Sacc[mt][nt][3] = p3;
                ps[mt][0] += p0 + p1; ps[mt][1] += p2 + p3;
                Oacc[mt][nt][0] *= alpha[mt][0]; Oacc[mt][nt][1] *= alpha[mt][0];
                Oacc[mt][nt][2] *= alpha[mt][1]; Oacc[mt][nt][3] *= alpha[mt][1];
            }
#pragma unroll
        for (int mt = 0; mt < 4; mt++)
#pragma unroll
            for (int hh = 0; hh < 2; hh++) {
                float v = ps[mt][hh];
                v += __shfl_xor_sync(0xffffffffu, v, 1);
                v += __shfl_xor_sync(0xffffffffu, v, 2);
                ps[mt][hh] = v;
            }
        if ((lane & 3) == 0) {
#pragma unroll
            for (int mt = 0; mt < 4; mt++)
#pragma unroll
                for (int hh = 0; hh < 2; hh++) {
                    int row = wm + mt * 16 + hh * 8 + (lane >> 2);
                    redS[row * 4 + (wid >> 1)] = ps[mt][hh];
                }
        }

        // ---- store P to smem as half (chunk = key cols 0-63 / 64-127) ----
        uint32_t pbase = Poff + ((wn >= 64) ? 16384u : 0u);
        int klc = (wn & 63);
#pragma unroll
        for (int mt = 0; mt < 4; mt++)
#pragma unroll
            for (int nt = 0; nt < 4; nt++) {
                int kc = klc + nt * 8 + q2;
                int r0 = wm + mt * 16 + (lane >> 2);
                uint32_t b0 = (uint32_t)(r0 * 128 + (((kc >> 3) ^ (r0 & 7)) << 4) + (kc & 7) * 2);
                *(__half2*)(smem + pbase + b0) = __floats2half2_rn(Sacc[mt][nt][0], Sacc[mt][nt][1]);
                int r1 = r0 + 8;
                uint32_t b1 = (uint32_t)(r1 * 128 + (((kc >> 3) ^ (r1 & 7)) << 4) + (kc & 7) * 2);
                *(__half2*)(smem + pbase + b1) = __floats2half2_rn(Sacc[mt][nt][2], Sacc[mt][nt][3]);
            }
        CP_WAIT1();          // V chunk0 landed; barrier below publishes it + P
        __syncthreads();

        // finish l update (redS published by the barrier above)
#pragma unroll
        for (int mt = 0; mt < 4; mt++)
#pragma unroll
            for (int hh = 0; hh < 2; hh++) {
                int row = wm + mt * 16 + hh * 8 + (lane >> 2);
                float s4 = redS[row * 4] + redS[row * 4 + 1] + redS[row * 4 + 2] + redS[row * 4 + 3];
                l_r[mt][hh] = l_r[mt][hh] * alpha[mt][hh] + s4;
                m_r[mt][hh] = mnew[mt][hh];
            }

        // ---- O += P @ V_blk ----
        compute_tile(sb + Poff, sb + SV0, Oacc, lane, wm, wn);
        CP_WAIT0();
        __syncthreads();
        compute_tile(sb + Poff + 16384, sb + SV1, Oacc, lane, wm, wn);
        __syncthreads();     // end-of-j: protect all slots before next j's fills
    }

    // ---- epilogue: O /= l, write half ----
#pragma unroll
    for (int mt = 0; mt < 4; mt++)
#pragma unroll
        for (int hh = 0; hh < 2; hh++) {
            float inv = 1.0f / l_r[mt][hh];
            int row = n * 128 + wm + mt * 16 + hh * 8 + (lane >> 2);
#pragma unroll
            for (int nt = 0; nt < 4; nt++) {
                int col = h * HD + wn + nt * 8 + q2;
                *(__half2*)(O + (size_t)row * (NH * HD) + col) =
                    __floats2half2_rn(Oacc[mt][nt][hh * 2] * inv, Oacc[mt][nt][hh * 2 + 1] * inv);
            }
        }
}

// ---------------- transpose float src[R][C] -> half dst[C][R] --------------
__global__ void transpose_f2h_kernel(const float* __restrict__ src, __half* __restrict__ dst,
                                     int R, int C) {
    __shared__ float t[32][33];
    int bx = blockIdx.x * 32, by = blockIdx.y * 32;
    int x = bx + threadIdx.x;
#pragma unroll
    for (int i = 0; i < 32; i += 8) {
        int y = by + threadIdx.y + i;
        t[threadIdx.y + i][threadIdx.x] = src[(size_t)y * C + x];
    }
    __syncthreads();
    int x2 = by + threadIdx.x;
#pragma unroll
    for (int i = 0; i < 32; i += 8) {
        int y2 = bx + threadIdx.y + i;
        dst[(size_t)y2 * R + x2] = __float2half_rn(t[threadIdx.x][threadIdx.y + i]);
    }
}

// ---------------- transpose half src (ld=sld) -> half dst[C][R] ------------
__global__ void transpose_h2h_kernel(const __half* __restrict__ src, __half* __restrict__ dst,
                                     int R, int C, int sld) {
    __shared__ __half t[32][33];
    int bx = blockIdx.x * 32, by = blockIdx.y * 32;
    int x = bx + threadIdx.x;
#pragma unroll
    for (int i = 0; i < 32; i += 8) {
        int y = by + threadIdx.y + i;
        t[threadIdx.y + i][threadIdx.x] = src[(size_t)y * sld + x];
    }
    __syncthreads();
    int x2 = by + threadIdx.x;
#pragma unroll
    for (int i = 0; i < 32; i += 8) {
        int y2 = bx + threadIdx.y + i;
        dst[(size_t)y2 * R + x2] = t[threadIdx.x][threadIdx.y + i];
    }
}

// ---------------- float -> half convert ------------------------------------
__global__ void f2h_kernel(const float* __restrict__ src, __half* __restrict__ dst, int n4) {
    int i = blockIdx.x * blockDim.x + threadIdx.x;
    if (i >= n4) return;
    float4 v = ((const float4*)src)[i];
    __half2 a = __floats2half2_rn(v.x, v.y);
    __half2 b = __floats2half2_rn(v.z, v.w);
    ((uint2*)dst)[i] = make_uint2(*(uint32_t*)&a, *(uint32_t*)&b);
}

// ---------------- RoPE on half slice (ld-strided), f32 math ----------------
__global__ void rope_h_kernel(__half* __restrict__ X,
                              const float* __restrict__ cosb,
                              const float* __restrict__ sinb,
                              int nheads, int ld, float scale) {
    int idx = blockIdx.x * blockDim.x + threadIdx.x;
    int total = S_LEN * nheads * 64;
    if (idx >= total) return;
    int d = idx & 63;
    int hh = (idx >> 6) % nheads;
    int s = idx / (64 * nheads);
    float c1 = cosb[s * HD + d],      s1 = sinb[s * HD + d];
    float c2 = cosb[s * HD + d + 64], s2 = sinb[s * HD + d + 64];
    __half* p = X + (size_t)s * ld + hh * HD + d;
    float x1 = __half2float(p[0]), x2 = __half2float(p[64]);
    p[0]  = __float2half_rn((x1 * c1 - x2 * s1) * scale);
    p[64] = __float2half_rn((x2 * c2 + x1 * s2) * scale);
}

// ---------------- launch --------------------------------------------------
extern "C" void kernel_launch(void* const* d_in, const int* in_sizes, int n_in,
                              void* d_out, int out_size) {
    const float* H    = (const float*)d_in[0];
    const float* mask = (const float*)d_in[1];
    const float* cosb = (const float*)d_in[2];
    const float* sinb = (const float*)d_in[3];
    const float* Wq   = (const float*)d_in[4];
    const float* Wk   = (const float*)d_in[5];
    const float* Wv   = (const float*)d_in[6];
    const float* Wo   = (const float*)d_in[7];
    float* out = (float*)d_out;

    __half *Hh, *QKV, *VTh, *Oh, *WqkvT, *WoT;
    cudaGetSymbolAddress((void**)&Hh, g_Hh);
    cudaGetSymbolAddress((void**)&QKV, g_QKVh);
    cudaGetSymbolAddress((void**)&VTh, g_VTh);
    cudaGetSymbolAddress((void**)&Oh, g_Oh);
    cudaGetSymbolAddress((void**)&WqkvT, g_WqkvT);
    cudaGetSymbolAddress((void**)&WoT, g_WoTh);

    cudaFuncSetAttribute(gemm_h_kernel<true>,  cudaFuncAttributeMaxDynamicSharedMemorySize, GEMM_SMEM);
    cudaFuncSetAttribute(gemm_h_kernel<false>, cudaFuncAttributeMaxDynamicSharedMemorySize, GEMM_SMEM);
    cudaFuncSetAttribute(flash_kernel,         cudaFuncAttributeMaxDynamicSharedMemorySize, FL_SMEM);

    dim3 tb(32, 8);
    f2h_kernel<<<(S_LEN * HID / 4 + 255) / 256, 256>>>(H, Hh, S_LEN * HID / 4);
    // concatenated [WqT; WkT; WvT]  (each dst row length = HID)
    transpose_f2h_kernel<<<dim3(64, 64), tb>>>(Wq, WqkvT, HID, NH * HD);
    transpose_f2h_kernel<<<dim3(16, 64), tb>>>(Wk, WqkvT + (size_t)(NH * HD) * HID, HID, NKV * HD);
    transpose_f2h_kernel<<<dim3(16, 64), tb>>>(Wv, WqkvT + (size_t)(NH * HD + NKV * HD) * HID, HID, NKV * HD);
    transpose_f2h_kernel<<<dim3(64, 64), tb>>>(Wo, WoT, NH * HD, HID);

    // fused QKV projection: [S,2048] @ [2048,3072]
    gemm_h_kernel<true><<<dim3(QKV_N / 128, 32), 256, GEMM_SMEM>>>(Hh, WqkvT, QKV, HID, QKV_N);

    // RoPE on Q (cols 0..2047) and K (cols 2048..2559) slices
    rope_h_kernel<<<(S_LEN * NH * 64 + 255) / 256, 256>>>(QKV, cosb, sinb, NH, QKV_N, SCALE);
    rope_h_kernel<<<(S_LEN * NKV * 64 + 255) / 256, 256>>>(QKV + NH * HD, cosb, sinb, NKV, QKV_N, 1.0f);

    // V^T from V slice (cols 2560..3071)
    transpose_h2h_kernel<<<dim3(16, 128), tb>>>(QKV + NH * HD + NKV * HD, VTh, S_LEN, NKV * HD, QKV_N);

    flash_kernel<<<dim3(NBLK, NH), 256, FL_SMEM>>>(QKV, QKV + NH * HD, VTh, mask, Oh);

    gemm_h_kernel<false><<<dim3(16, 32), 256, GEMM_SMEM>>>(Oh, WoT, out, NH * HD, HID);
}